// round 1
// baseline (speedup 1.0000x reference)
#include <cuda_runtime.h>
#include <cuda_bf16.h>
#include <math.h>

// ---------------------------------------------------------------------------
// Problem constants
// ---------------------------------------------------------------------------
#define D_MODEL 1024
#define DFF     4096
#define NLAYERS 8
#define BATCH   4
#define SEQ     2048
#define NTOK    (BATCH * SEQ)      // 8192
#define EPS     1e-5f

// ---------------------------------------------------------------------------
// Device scratch (allocation-free rule: __device__ globals)
// ---------------------------------------------------------------------------
__device__ float g_ln [NTOK * D_MODEL];           // 32 MB
__device__ float g_q  [NTOK * D_MODEL];           // 32 MB
__device__ float g_k  [NTOK * D_MODEL];           // 32 MB
__device__ float g_v  [NTOK * D_MODEL];           // 32 MB
__device__ float g_sc [BATCH * SEQ * SEQ];        // 64 MB
__device__ float g_hid[NTOK * DFF];               // 128 MB

// ---------------------------------------------------------------------------
// Embedding + sinusoidal positional encoding
// ---------------------------------------------------------------------------
__global__ __launch_bounds__(256)
void embed_kernel(const int* __restrict__ tokens,
                  const float* __restrict__ emb,
                  float* __restrict__ out)
{
    int row = blockIdx.x;                 // 0..8191
    int s   = row & (SEQ - 1);
    int tok = tokens[row];
    int d   = threadIdx.x * 4;

    float4 e = *(const float4*)&emb[(size_t)tok * D_MODEL + d];
    float o[4] = { e.x, e.y, e.z, e.w };
#pragma unroll
    for (int i = 0; i < 4; i++) {
        int dd = d + i;
        float freq = expf((float)(dd & ~1) * (-9.210340371976184f / (float)D_MODEL));
        float a = (float)s * freq;
        o[i] += (dd & 1) ? cosf(a) : sinf(a);
    }
    *(float4*)&out[(size_t)row * D_MODEL + d] = make_float4(o[0], o[1], o[2], o[3]);
}

// ---------------------------------------------------------------------------
// LayerNorm: one block per row (1024 elems, 256 threads x float4).
// Two-pass (mean, then mean((x-mu)^2)) matching the reference formulation.
// ---------------------------------------------------------------------------
__global__ __launch_bounds__(256)
void ln_kernel(const float* __restrict__ x,
               const float* __restrict__ g,
               const float* __restrict__ b,
               float* __restrict__ out)
{
    __shared__ float red[8];
    __shared__ float s_stat;

    int row = blockIdx.x;
    int tid = threadIdx.x;
    const float4* xr = (const float4*)(x + (size_t)row * D_MODEL);
    float4 v = xr[tid];

    // pass 1: mean
    float s = v.x + v.y + v.z + v.w;
#pragma unroll
    for (int o = 16; o > 0; o >>= 1) s += __shfl_xor_sync(0xffffffffu, s, o);
    if ((tid & 31) == 0) red[tid >> 5] = s;
    __syncthreads();
    if (tid == 0) {
        float t = 0.f;
#pragma unroll
        for (int i = 0; i < 8; i++) t += red[i];
        s_stat = t * (1.0f / D_MODEL);
    }
    __syncthreads();
    float mean = s_stat;

    float4 d;
    d.x = v.x - mean; d.y = v.y - mean; d.z = v.z - mean; d.w = v.w - mean;

    // pass 2: variance
    float s2 = d.x * d.x + d.y * d.y + d.z * d.z + d.w * d.w;
#pragma unroll
    for (int o = 16; o > 0; o >>= 1) s2 += __shfl_xor_sync(0xffffffffu, s2, o);
    if ((tid & 31) == 0) red[tid >> 5] = s2;
    __syncthreads();
    if (tid == 0) {
        float t = 0.f;
#pragma unroll
        for (int i = 0; i < 8; i++) t += red[i];
        s_stat = rsqrtf(t * (1.0f / D_MODEL) + EPS);
    }
    __syncthreads();
    float rstd = s_stat;

    float4 gg = *(const float4*)&g[tid * 4];
    float4 bb = *(const float4*)&b[tid * 4];
    float4 o4;
    o4.x = d.x * rstd * gg.x + bb.x;
    o4.y = d.y * rstd * gg.y + bb.y;
    o4.z = d.z * rstd * gg.z + bb.z;
    o4.w = d.w * rstd * gg.w + bb.w;
    *(float4*)(out + (size_t)row * D_MODEL + tid * 4) = o4;
}

// ---------------------------------------------------------------------------
// Softmax over rows of length SEQ (2048). One block per row, values stay in
// registers (8 per thread).
// ---------------------------------------------------------------------------
__global__ __launch_bounds__(256)
void softmax_kernel(float* __restrict__ sc)
{
    __shared__ float red[8];
    __shared__ float s_val;

    size_t row = blockIdx.x;
    float4* p = (float4*)(sc + row * SEQ);
    int tid = threadIdx.x;

    float4 v0 = p[tid];
    float4 v1 = p[tid + 256];

    float m = fmaxf(fmaxf(fmaxf(v0.x, v0.y), fmaxf(v0.z, v0.w)),
                    fmaxf(fmaxf(v1.x, v1.y), fmaxf(v1.z, v1.w)));
#pragma unroll
    for (int o = 16; o > 0; o >>= 1) m = fmaxf(m, __shfl_xor_sync(0xffffffffu, m, o));
    if ((tid & 31) == 0) red[tid >> 5] = m;
    __syncthreads();
    if (tid == 0) {
        float t = red[0];
#pragma unroll
        for (int i = 1; i < 8; i++) t = fmaxf(t, red[i]);
        s_val = t;
    }
    __syncthreads();
    m = s_val;

    v0.x = expf(v0.x - m); v0.y = expf(v0.y - m);
    v0.z = expf(v0.z - m); v0.w = expf(v0.w - m);
    v1.x = expf(v1.x - m); v1.y = expf(v1.y - m);
    v1.z = expf(v1.z - m); v1.w = expf(v1.w - m);

    float s = v0.x + v0.y + v0.z + v0.w + v1.x + v1.y + v1.z + v1.w;
#pragma unroll
    for (int o = 16; o > 0; o >>= 1) s += __shfl_xor_sync(0xffffffffu, s, o);
    if ((tid & 31) == 0) red[tid >> 5] = s;
    __syncthreads();
    if (tid == 0) {
        float t = 0.f;
#pragma unroll
        for (int i = 0; i < 8; i++) t += red[i];
        s_val = t;
    }
    __syncthreads();
    float inv = 1.0f / s_val;

    v0.x *= inv; v0.y *= inv; v0.z *= inv; v0.w *= inv;
    v1.x *= inv; v1.y *= inv; v1.z *= inv; v1.w *= inv;
    p[tid]       = v0;
    p[tid + 256] = v1;
}

// ---------------------------------------------------------------------------
// Generic tiled SGEMM. C[M,N] = alpha * A[M,K] @ op(B) (+ bias[N]) (relu)
// (+ residual[M,N]). op(B) = B[K,N] (NN) or B[N,K]^T (NT).
// Block tile 128x128, K-tile 16, 256 threads, 8x8 per thread.
// Batched via blockIdx.z with element strides sA/sB/sC (residual shares sC).
// All problem dims are multiples of the tiles -> no bounds checks.
// ---------------------------------------------------------------------------
#define BM 128
#define BN 128
#define BKT 16

template<bool TRANSB, bool RELU>
__global__ __launch_bounds__(256)
void gemm_kernel(const float* __restrict__ A,
                 const float* __restrict__ B,
                 float* __restrict__ C,
                 const float* __restrict__ bias,
                 const float* __restrict__ residual,
                 int M, int N, int K, float alpha,
                 long long sA, long long sB, long long sC)
{
    __shared__ float As[BKT][BM];
    __shared__ float Bs[BKT][BN];

    long long bz = blockIdx.z;
    A += bz * sA;
    B += bz * sB;
    C += bz * sC;
    if (residual) residual += bz * sC;

    const int rowBase = blockIdx.y * BM;
    const int colBase = blockIdx.x * BN;
    const int tid = threadIdx.x;
    const int tx = tid & 15;        // 0..15 -> column micro-tile
    const int ty = tid >> 4;        // 0..15 -> row micro-tile

    float acc[8][8];
#pragma unroll
    for (int i = 0; i < 8; i++)
#pragma unroll
        for (int j = 0; j < 8; j++) acc[i][j] = 0.f;

    for (int kb = 0; kb < K; kb += BKT) {
        // ---- load A tile (128 rows x 16 cols) as 512 float4, transposed store
#pragma unroll
        for (int l = 0; l < 2; l++) {
            int id  = l * 256 + tid;
            int row = id >> 2;
            int c4  = (id & 3) * 4;
            float4 va = *(const float4*)&A[(size_t)(rowBase + row) * K + kb + c4];
            As[c4 + 0][row] = va.x;
            As[c4 + 1][row] = va.y;
            As[c4 + 2][row] = va.z;
            As[c4 + 3][row] = va.w;
        }
        // ---- load B tile
        if (!TRANSB) {
            // B[K,N]: 16 rows x 128 cols
#pragma unroll
            for (int l = 0; l < 2; l++) {
                int id  = l * 256 + tid;
                int row = id >> 5;
                int c4  = (id & 31) * 4;
                float4 vb = *(const float4*)&B[(size_t)(kb + row) * N + colBase + c4];
                *(float4*)&Bs[row][c4] = vb;
            }
        } else {
            // B[N,K]: need Bs[k][n] = B[n][k]
#pragma unroll
            for (int l = 0; l < 2; l++) {
                int id = l * 256 + tid;
                int n  = id >> 2;
                int c4 = (id & 3) * 4;
                float4 vb = *(const float4*)&B[(size_t)(colBase + n) * K + kb + c4];
                Bs[c4 + 0][n] = vb.x;
                Bs[c4 + 1][n] = vb.y;
                Bs[c4 + 2][n] = vb.z;
                Bs[c4 + 3][n] = vb.w;
            }
        }
        __syncthreads();

#pragma unroll
        for (int kk = 0; kk < BKT; kk++) {
            float4 a0 = *(const float4*)&As[kk][ty * 8];
            float4 a1 = *(const float4*)&As[kk][ty * 8 + 4];
            float4 b0 = *(const float4*)&Bs[kk][tx * 8];
            float4 b1 = *(const float4*)&Bs[kk][tx * 8 + 4];
            float a[8] = { a0.x, a0.y, a0.z, a0.w, a1.x, a1.y, a1.z, a1.w };
            float b[8] = { b0.x, b0.y, b0.z, b0.w, b1.x, b1.y, b1.z, b1.w };
#pragma unroll
            for (int i = 0; i < 8; i++)
#pragma unroll
                for (int j = 0; j < 8; j++)
                    acc[i][j] = fmaf(a[i], b[j], acc[i][j]);
        }
        __syncthreads();
    }

    // ---- epilogue: alpha, bias, relu, residual
#pragma unroll
    for (int i = 0; i < 8; i++) {
        int row = rowBase + ty * 8 + i;
#pragma unroll
        for (int j = 0; j < 8; j += 4) {
            int col = colBase + tx * 8 + j;
            float4 r;
            r.x = alpha * acc[i][j + 0];
            r.y = alpha * acc[i][j + 1];
            r.z = alpha * acc[i][j + 2];
            r.w = alpha * acc[i][j + 3];
            if (bias) {
                float4 bb = *(const float4*)&bias[col];
                r.x += bb.x; r.y += bb.y; r.z += bb.z; r.w += bb.w;
            }
            if (RELU) {
                r.x = fmaxf(r.x, 0.f); r.y = fmaxf(r.y, 0.f);
                r.z = fmaxf(r.z, 0.f); r.w = fmaxf(r.w, 0.f);
            }
            if (residual) {
                float4 rr = *(const float4*)&residual[(size_t)row * N + col];
                r.x += rr.x; r.y += rr.y; r.z += rr.z; r.w += rr.w;
            }
            *(float4*)&C[(size_t)row * N + col] = r;
        }
    }
}

// ---------------------------------------------------------------------------
// Host launcher
// ---------------------------------------------------------------------------
extern "C" void kernel_launch(void* const* d_in, const int* in_sizes, int n_in,
                              void* d_out, int out_size)
{
    const int*   tokens = (const int*)  d_in[0];
    const float* emb    = (const float*)d_in[1];
    const float* Wq     = (const float*)d_in[2];
    const float* bq     = (const float*)d_in[3];
    const float* Wk     = (const float*)d_in[4];
    const float* bk     = (const float*)d_in[5];
    const float* Wv     = (const float*)d_in[6];
    const float* bv     = (const float*)d_in[7];
    const float* g1     = (const float*)d_in[8];
    const float* beta1  = (const float*)d_in[9];
    const float* g2     = (const float*)d_in[10];
    const float* beta2  = (const float*)d_in[11];
    const float* W1     = (const float*)d_in[12];
    const float* bm1    = (const float*)d_in[13];
    const float* W2     = (const float*)d_in[14];
    const float* bm2    = (const float*)d_in[15];

    float* x = (float*)d_out;                 // residual stream lives in d_out

    float *ln, *q, *k, *v, *sc, *hid;
    cudaGetSymbolAddress((void**)&ln,  g_ln);
    cudaGetSymbolAddress((void**)&q,   g_q);
    cudaGetSymbolAddress((void**)&k,   g_k);
    cudaGetSymbolAddress((void**)&v,   g_v);
    cudaGetSymbolAddress((void**)&sc,  g_sc);
    cudaGetSymbolAddress((void**)&hid, g_hid);

    const long long TD  = (long long)SEQ * D_MODEL;      // per-batch token-feature stride
    const long long SS  = (long long)SEQ * SEQ;          // per-batch score stride
    const float inv_sqrt_d = 0.03125f;                   // 1/sqrt(1024)

    // x = emb[tokens] + PE
    embed_kernel<<<NTOK, 256>>>(tokens, emb, x);

    for (int l = 0; l < NLAYERS; l++) {
        const float* wq = Wq + (size_t)l * D_MODEL * D_MODEL;
        const float* wk = Wk + (size_t)l * D_MODEL * D_MODEL;
        const float* wv = Wv + (size_t)l * D_MODEL * D_MODEL;
        const float* w1 = W1 + (size_t)l * D_MODEL * DFF;
        const float* w2 = W2 + (size_t)l * DFF * D_MODEL;

        // h = LN(x)
        ln_kernel<<<NTOK, 256>>>(x, g1 + l * D_MODEL, beta1 + l * D_MODEL, ln);

        // q,k,v = h@W + b     [8192,1024] @ [1024,1024]
        dim3 gQKV(D_MODEL / BN, NTOK / BM, 1);
        gemm_kernel<false, false><<<gQKV, 256>>>(ln, wq, q, bq + l * D_MODEL, nullptr,
                                                 NTOK, D_MODEL, D_MODEL, 1.f, 0, 0, 0);
        gemm_kernel<false, false><<<gQKV, 256>>>(ln, wk, k, bk + l * D_MODEL, nullptr,
                                                 NTOK, D_MODEL, D_MODEL, 1.f, 0, 0, 0);
        gemm_kernel<false, false><<<gQKV, 256>>>(ln, wv, v, bv + l * D_MODEL, nullptr,
                                                 NTOK, D_MODEL, D_MODEL, 1.f, 0, 0, 0);

        // scores = q @ k^T / sqrt(D)   batched [2048,1024]x[2048,1024]^T
        dim3 gSC(SEQ / BN, SEQ / BM, BATCH);
        gemm_kernel<true, false><<<gSC, 256>>>(q, k, sc, nullptr, nullptr,
                                               SEQ, SEQ, D_MODEL, inv_sqrt_d,
                                               TD, TD, SS);

        softmax_kernel<<<BATCH * SEQ, 256>>>(sc);

        // x = x + attn @ v   batched [2048,2048]x[2048,1024], residual fused
        dim3 gAV(D_MODEL / BN, SEQ / BM, BATCH);
        gemm_kernel<false, false><<<gAV, 256>>>(sc, v, x, nullptr, x,
                                                SEQ, D_MODEL, SEQ, 1.f,
                                                SS, TD, TD);

        // h2 = LN(x)
        ln_kernel<<<NTOK, 256>>>(x, g2 + l * D_MODEL, beta2 + l * D_MODEL, ln);

        // hid = relu(h2 @ W1 + bm1)   [8192,1024]x[1024,4096]
        dim3 gM1(DFF / BN, NTOK / BM, 1);
        gemm_kernel<false, true><<<gM1, 256>>>(ln, w1, hid, bm1 + l * DFF, nullptr,
                                               NTOK, DFF, D_MODEL, 1.f, 0, 0, 0);

        // x = x + hid @ W2 + bm2      [8192,4096]x[4096,1024], residual fused
        dim3 gM2(D_MODEL / BN, NTOK / BM, 1);
        gemm_kernel<false, false><<<gM2, 256>>>(hid, w2, x, bm2 + l * D_MODEL, x,
                                                NTOK, D_MODEL, DFF, 1.f, 0, 0, 0);
    }
}

// round 3
// speedup vs baseline: 2.0101x; 2.0101x over previous
#include <cuda_runtime.h>
#include <cuda_bf16.h>
#include <math.h>
#include <stdint.h>

// ---------------------------------------------------------------------------
// Problem constants
// ---------------------------------------------------------------------------
#define D_MODEL 1024
#define DFF     4096
#define NLAYERS 8
#define BATCH   4
#define SEQ     2048
#define NTOK    (BATCH * SEQ)      // 8192
#define EPS     1e-5f

// ---------------------------------------------------------------------------
// Device scratch (allocation-free rule: __device__ globals)
// ---------------------------------------------------------------------------
__device__ float g_ln [NTOK * D_MODEL];           // 32 MB
__device__ float g_q  [NTOK * D_MODEL];           // 32 MB
__device__ float g_k  [NTOK * D_MODEL];           // 32 MB
__device__ float g_v  [NTOK * D_MODEL];           // 32 MB
__device__ float g_sc [BATCH * SEQ * SEQ];        // 64 MB
__device__ float g_hid[NTOK * DFF];               // 128 MB

// ---------------------------------------------------------------------------
// PTX helpers: warp-level bf16 MMA (sm_80+ PTX, works on plain sm_103 target)
// ---------------------------------------------------------------------------
__device__ __forceinline__ uint32_t smem_u32(const void* p) {
    uint32_t a;
    asm("{ .reg .u64 t; cvta.to.shared.u64 t, %1; cvt.u32.u64 %0, t; }"
        : "=r"(a) : "l"(p));
    return a;
}

__device__ __forceinline__ void ldsm_x4(uint32_t* r, uint32_t addr) {
    asm volatile("ldmatrix.sync.aligned.m8n8.x4.shared.b16 {%0,%1,%2,%3}, [%4];"
                 : "=r"(r[0]), "=r"(r[1]), "=r"(r[2]), "=r"(r[3]) : "r"(addr));
}

__device__ __forceinline__ void ldsm_x4_t(uint32_t* r, uint32_t addr) {
    asm volatile("ldmatrix.sync.aligned.m8n8.x4.trans.shared.b16 {%0,%1,%2,%3}, [%4];"
                 : "=r"(r[0]), "=r"(r[1]), "=r"(r[2]), "=r"(r[3]) : "r"(addr));
}

__device__ __forceinline__ void mma_bf16(float* c, const uint32_t* a, const uint32_t* b) {
    asm volatile(
        "mma.sync.aligned.m16n8k16.row.col.f32.bf16.bf16.f32 "
        "{%0,%1,%2,%3}, {%4,%5,%6,%7}, {%8,%9}, {%0,%1,%2,%3};"
        : "+f"(c[0]), "+f"(c[1]), "+f"(c[2]), "+f"(c[3])
        : "r"(a[0]), "r"(a[1]), "r"(a[2]), "r"(a[3]), "r"(b[0]), "r"(b[1]));
}

__device__ __forceinline__ void sts_v2(uint32_t addr, uint32_t a, uint32_t b) {
    asm volatile("st.shared.v2.b32 [%0], {%1, %2};" :: "r"(addr), "r"(a), "r"(b) : "memory");
}

// pack 4 floats into hi-bf16 pair and lo-bf16 pair (2x u32 each)
__device__ __forceinline__ void split4(const float4 v, uint32_t* hi, uint32_t* lo) {
    __nv_bfloat16 h0 = __float2bfloat16(v.x);
    __nv_bfloat16 h1 = __float2bfloat16(v.y);
    __nv_bfloat16 h2 = __float2bfloat16(v.z);
    __nv_bfloat16 h3 = __float2bfloat16(v.w);
    __nv_bfloat16 l0 = __float2bfloat16(v.x - __bfloat162float(h0));
    __nv_bfloat16 l1 = __float2bfloat16(v.y - __bfloat162float(h1));
    __nv_bfloat16 l2 = __float2bfloat16(v.z - __bfloat162float(h2));
    __nv_bfloat16 l3 = __float2bfloat16(v.w - __bfloat162float(h3));
    hi[0] = ((uint32_t)__bfloat16_as_ushort(h1) << 16) | __bfloat16_as_ushort(h0);
    hi[1] = ((uint32_t)__bfloat16_as_ushort(h3) << 16) | __bfloat16_as_ushort(h2);
    lo[0] = ((uint32_t)__bfloat16_as_ushort(l1) << 16) | __bfloat16_as_ushort(l0);
    lo[1] = ((uint32_t)__bfloat16_as_ushort(l3) << 16) | __bfloat16_as_ushort(l2);
}

// ---------------------------------------------------------------------------
// Elementwise kernels
// ---------------------------------------------------------------------------
__global__ __launch_bounds__(256)
void embed_kernel(const int* __restrict__ tokens,
                  const float* __restrict__ emb,
                  float* __restrict__ out)
{
    int row = blockIdx.x;
    int s   = row & (SEQ - 1);
    int tok = tokens[row];
    int d   = threadIdx.x * 4;

    float4 e = *(const float4*)&emb[(size_t)tok * D_MODEL + d];
    float o[4] = { e.x, e.y, e.z, e.w };
#pragma unroll
    for (int i = 0; i < 4; i++) {
        int dd = d + i;
        float freq = expf((float)(dd & ~1) * (-9.210340371976184f / (float)D_MODEL));
        float a = (float)s * freq;
        o[i] += (dd & 1) ? cosf(a) : sinf(a);
    }
    *(float4*)&out[(size_t)row * D_MODEL + d] = make_float4(o[0], o[1], o[2], o[3]);
}

__global__ __launch_bounds__(256)
void ln_kernel(const float* __restrict__ x,
               const float* __restrict__ g,
               const float* __restrict__ b,
               float* __restrict__ out)
{
    __shared__ float red[8];
    __shared__ float s_stat;

    int row = blockIdx.x;
    int tid = threadIdx.x;
    const float4* xr = (const float4*)(x + (size_t)row * D_MODEL);
    float4 v = xr[tid];

    float s = v.x + v.y + v.z + v.w;
#pragma unroll
    for (int o = 16; o > 0; o >>= 1) s += __shfl_xor_sync(0xffffffffu, s, o);
    if ((tid & 31) == 0) red[tid >> 5] = s;
    __syncthreads();
    if (tid == 0) {
        float t = 0.f;
#pragma unroll
        for (int i = 0; i < 8; i++) t += red[i];
        s_stat = t * (1.0f / D_MODEL);
    }
    __syncthreads();
    float mean = s_stat;

    float4 d;
    d.x = v.x - mean; d.y = v.y - mean; d.z = v.z - mean; d.w = v.w - mean;

    float s2 = d.x * d.x + d.y * d.y + d.z * d.z + d.w * d.w;
#pragma unroll
    for (int o = 16; o > 0; o >>= 1) s2 += __shfl_xor_sync(0xffffffffu, s2, o);
    if ((tid & 31) == 0) red[tid >> 5] = s2;
    __syncthreads();
    if (tid == 0) {
        float t = 0.f;
#pragma unroll
        for (int i = 0; i < 8; i++) t += red[i];
        s_stat = rsqrtf(t * (1.0f / D_MODEL) + EPS);
    }
    __syncthreads();
    float rstd = s_stat;

    float4 gg = *(const float4*)&g[tid * 4];
    float4 bb = *(const float4*)&b[tid * 4];
    float4 o4;
    o4.x = d.x * rstd * gg.x + bb.x;
    o4.y = d.y * rstd * gg.y + bb.y;
    o4.z = d.z * rstd * gg.z + bb.z;
    o4.w = d.w * rstd * gg.w + bb.w;
    *(float4*)(out + (size_t)row * D_MODEL + tid * 4) = o4;
}

__global__ __launch_bounds__(256)
void softmax_kernel(float* __restrict__ sc)
{
    __shared__ float red[8];
    __shared__ float s_val;

    size_t row = blockIdx.x;
    float4* p = (float4*)(sc + row * SEQ);
    int tid = threadIdx.x;

    float4 v0 = p[tid];
    float4 v1 = p[tid + 256];

    float m = fmaxf(fmaxf(fmaxf(v0.x, v0.y), fmaxf(v0.z, v0.w)),
                    fmaxf(fmaxf(v1.x, v1.y), fmaxf(v1.z, v1.w)));
#pragma unroll
    for (int o = 16; o > 0; o >>= 1) m = fmaxf(m, __shfl_xor_sync(0xffffffffu, m, o));
    if ((tid & 31) == 0) red[tid >> 5] = m;
    __syncthreads();
    if (tid == 0) {
        float t = red[0];
#pragma unroll
        for (int i = 1; i < 8; i++) t = fmaxf(t, red[i]);
        s_val = t;
    }
    __syncthreads();
    m = s_val;

    v0.x = expf(v0.x - m); v0.y = expf(v0.y - m);
    v0.z = expf(v0.z - m); v0.w = expf(v0.w - m);
    v1.x = expf(v1.x - m); v1.y = expf(v1.y - m);
    v1.z = expf(v1.z - m); v1.w = expf(v1.w - m);

    float s = v0.x + v0.y + v0.z + v0.w + v1.x + v1.y + v1.z + v1.w;
#pragma unroll
    for (int o = 16; o > 0; o >>= 1) s += __shfl_xor_sync(0xffffffffu, s, o);
    if ((tid & 31) == 0) red[tid >> 5] = s;
    __syncthreads();
    if (tid == 0) {
        float t = 0.f;
#pragma unroll
        for (int i = 0; i < 8; i++) t += red[i];
        s_val = t;
    }
    __syncthreads();
    float inv = 1.0f / s_val;

    v0.x *= inv; v0.y *= inv; v0.z *= inv; v0.w *= inv;
    v1.x *= inv; v1.y *= inv; v1.z *= inv; v1.w *= inv;
    p[tid]       = v0;
    p[tid + 256] = v1;
}

// ---------------------------------------------------------------------------
// Split-bf16 warp-MMA GEMM.
// C[M,N] = alpha * A[M,K] @ op(B) (+bias) (relu) (+residual)
//   TRANSB=1: op(B)=B[N,K]^T  (smem [n][k] stride 40, ldmatrix non-trans)
//   TRANSB=0: op(B)=B[K,N]    (smem [k][n] stride 136, ldmatrix .trans)
// A smem [m][k] stride 40. Block tile 128x128, BK=32, 8 warps (4M x 2N),
// warp tile 32x64, m16n8k16 bf16 MMA, 3 split terms (HH+HL+LH), fp32 acc.
// Double-buffered smem + register prefetch of next chunk.
// ---------------------------------------------------------------------------
#define A_STRIDE_B 80          // bytes per A/B-NT row (40 bf16)
#define A_BYTES    10240       // 128 * 80
#define BNN_STRIDE_B 272       // bytes per B-NN row (136 bf16)
#define BNN_BYTES  8704        // 32 * 272
#define STAGE_B    40960       // max(2*A_BYTES + 2*A_BYTES, 2*A_BYTES + 2*BNN_BYTES)
#define TC_SMEM    (2 * STAGE_B)   // 81920

template<bool TRANSB, bool RELU>
__global__ __launch_bounds__(256, 1)
void tc_gemm(const float* __restrict__ A,
             const float* __restrict__ B,
             float* __restrict__ C,
             const float* __restrict__ bias,
             const float* __restrict__ residual,
             int M, int N, int K, float alpha,
             long long strA, long long strB, long long strC)
{
    extern __shared__ char smem[];
    const uint32_t sb = smem_u32(smem);
    const int tid  = threadIdx.x;
    const int wid  = tid >> 5;
    const int lane = tid & 31;
    const int wm   = wid >> 1;      // 0..3  (M warp)
    const int wn   = wid & 1;       // 0..1  (N warp)

    long long bz = blockIdx.z;
    A += bz * strA;
    B += bz * strB;
    C += bz * strC;
    const float* Rres = residual ? residual + bz * strC : nullptr;

    const int rowBase = blockIdx.y * 128;
    const int colBase = blockIdx.x * 128;

    float acc[2][8][4];
#pragma unroll
    for (int i = 0; i < 2; i++)
#pragma unroll
        for (int j = 0; j < 8; j++)
#pragma unroll
            for (int t = 0; t < 4; t++) acc[i][j][t] = 0.f;

    const int nch = K >> 5;

    float4 pa[4], pb[4];

    // prefetch chunk 0
    {
        const float* Ap = A + (size_t)rowBase * K;
#pragma unroll
        for (int i = 0; i < 4; i++) {
            int idx = tid + (i << 8);
            pa[i] = *(const float4*)(Ap + (size_t)(idx >> 3) * K + ((idx & 7) << 2));
        }
        if (TRANSB) {
            const float* Bp = B + (size_t)colBase * K;
#pragma unroll
            for (int i = 0; i < 4; i++) {
                int idx = tid + (i << 8);
                pb[i] = *(const float4*)(Bp + (size_t)(idx >> 3) * K + ((idx & 7) << 2));
            }
        } else {
            const float* Bp = B + colBase;
#pragma unroll
            for (int i = 0; i < 4; i++) {
                int idx = tid + (i << 8);
                pb[i] = *(const float4*)(Bp + (size_t)(idx >> 5) * N + ((idx & 31) << 2));
            }
        }
    }

    for (int c = 0; c < nch; c++) {
        const uint32_t stg = sb + (uint32_t)(c & 1) * STAGE_B;
        const uint32_t aH = stg;
        const uint32_t aL = stg + A_BYTES;
        const uint32_t bH = stg + 2 * A_BYTES;
        const uint32_t bL = bH + (TRANSB ? A_BYTES : BNN_BYTES);

        // ---- convert prefetched regs -> smem (bf16 hi/lo)
#pragma unroll
        for (int i = 0; i < 4; i++) {
            int idx = tid + (i << 8);
            uint32_t hi[2], lo[2];
            split4(pa[i], hi, lo);
            uint32_t off = (uint32_t)(idx >> 3) * A_STRIDE_B + ((idx & 7) << 3);
            sts_v2(aH + off, hi[0], hi[1]);
            sts_v2(aL + off, lo[0], lo[1]);
        }
#pragma unroll
        for (int i = 0; i < 4; i++) {
            int idx = tid + (i << 8);
            uint32_t hi[2], lo[2];
            split4(pb[i], hi, lo);
            uint32_t off;
            if (TRANSB) off = (uint32_t)(idx >> 3) * A_STRIDE_B + ((idx & 7) << 3);
            else        off = (uint32_t)(idx >> 5) * BNN_STRIDE_B + ((idx & 31) << 3);
            sts_v2(bH + off, hi[0], hi[1]);
            sts_v2(bL + off, lo[0], lo[1]);
        }

        // ---- prefetch next chunk while stores/compute happen
        if (c + 1 < nch) {
            const float* Ap = A + (size_t)rowBase * K + (size_t)(c + 1) * 32;
#pragma unroll
            for (int i = 0; i < 4; i++) {
                int idx = tid + (i << 8);
                pa[i] = *(const float4*)(Ap + (size_t)(idx >> 3) * K + ((idx & 7) << 2));
            }
            if (TRANSB) {
                const float* Bp = B + (size_t)colBase * K + (size_t)(c + 1) * 32;
#pragma unroll
                for (int i = 0; i < 4; i++) {
                    int idx = tid + (i << 8);
                    pb[i] = *(const float4*)(Bp + (size_t)(idx >> 3) * K + ((idx & 7) << 2));
                }
            } else {
                const float* Bp = B + (size_t)((c + 1) * 32) * N + colBase;
#pragma unroll
                for (int i = 0; i < 4; i++) {
                    int idx = tid + (i << 8);
                    pb[i] = *(const float4*)(Bp + (size_t)(idx >> 5) * N + ((idx & 31) << 2));
                }
            }
        }

        __syncthreads();

        // ---- compute: 2 k16 steps x (2 m16) x (8 n8) x 3 splits
#pragma unroll
        for (int ks = 0; ks < 2; ks++) {
            uint32_t ah[2][4], al[2][4];
#pragma unroll
            for (int mt = 0; mt < 2; mt++) {
                uint32_t off = (uint32_t)(wm * 32 + mt * 16 + (lane & 15)) * A_STRIDE_B
                             + (uint32_t)(ks * 16 + (lane >> 4) * 8) * 2;
                ldsm_x4(ah[mt], aH + off);
                ldsm_x4(al[mt], aL + off);
            }
#pragma unroll
            for (int p = 0; p < 4; p++) {
                uint32_t bh[4], bl[4];
                if (TRANSB) {
                    uint32_t off = (uint32_t)(wn * 64 + p * 16 + (lane & 7) + ((lane >> 4) & 1) * 8) * A_STRIDE_B
                                 + (uint32_t)(ks * 16 + ((lane >> 3) & 1) * 8) * 2;
                    ldsm_x4(bh, bH + off);
                    ldsm_x4(bl, bL + off);
                } else {
                    uint32_t off = (uint32_t)(ks * 16 + (lane & 7) + ((lane >> 3) & 1) * 8) * BNN_STRIDE_B
                                 + (uint32_t)(wn * 64 + p * 16 + (lane >> 4) * 8) * 2;
                    ldsm_x4_t(bh, bH + off);
                    ldsm_x4_t(bl, bL + off);
                }
#pragma unroll
                for (int mt = 0; mt < 2; mt++) {
#pragma unroll
                    for (int g = 0; g < 2; g++) {
                        float* a4 = acc[mt][p * 2 + g];
                        mma_bf16(a4, ah[mt], bh + 2 * g);   // hi*hi
                        mma_bf16(a4, ah[mt], bl + 2 * g);   // hi*lo
                        mma_bf16(a4, al[mt], bh + 2 * g);   // lo*hi
                    }
                }
            }
        }
        __syncthreads();
    }

    // ---- epilogue: direct register stores (float2 per row fragment)
#pragma unroll
    for (int mt = 0; mt < 2; mt++) {
        int r0 = rowBase + wm * 32 + mt * 16 + (lane >> 2);
#pragma unroll
        for (int ng = 0; ng < 8; ng++) {
            int col = colBase + wn * 64 + ng * 8 + (lane & 3) * 2;
            float2 v0, v1;
            v0.x = alpha * acc[mt][ng][0];
            v0.y = alpha * acc[mt][ng][1];
            v1.x = alpha * acc[mt][ng][2];
            v1.y = alpha * acc[mt][ng][3];
            if (bias) {
                float2 bb = *(const float2*)&bias[col];
                v0.x += bb.x; v0.y += bb.y;
                v1.x += bb.x; v1.y += bb.y;
            }
            if (RELU) {
                v0.x = fmaxf(v0.x, 0.f); v0.y = fmaxf(v0.y, 0.f);
                v1.x = fmaxf(v1.x, 0.f); v1.y = fmaxf(v1.y, 0.f);
            }
            if (Rres) {
                float2 q0 = *(const float2*)&Rres[(size_t)r0 * N + col];
                float2 q1 = *(const float2*)&Rres[(size_t)(r0 + 8) * N + col];
                v0.x += q0.x; v0.y += q0.y;
                v1.x += q1.x; v1.y += q1.y;
            }
            *(float2*)&C[(size_t)r0 * N + col]       = v0;
            *(float2*)&C[(size_t)(r0 + 8) * N + col] = v1;
        }
    }
}

// ---------------------------------------------------------------------------
// Host launcher
// ---------------------------------------------------------------------------
extern "C" void kernel_launch(void* const* d_in, const int* in_sizes, int n_in,
                              void* d_out, int out_size)
{
    const int*   tokens = (const int*)  d_in[0];
    const float* emb    = (const float*)d_in[1];
    const float* Wq     = (const float*)d_in[2];
    const float* bq     = (const float*)d_in[3];
    const float* Wk     = (const float*)d_in[4];
    const float* bk     = (const float*)d_in[5];
    const float* Wv     = (const float*)d_in[6];
    const float* bv     = (const float*)d_in[7];
    const float* g1     = (const float*)d_in[8];
    const float* beta1  = (const float*)d_in[9];
    const float* g2     = (const float*)d_in[10];
    const float* beta2  = (const float*)d_in[11];
    const float* W1     = (const float*)d_in[12];
    const float* bm1    = (const float*)d_in[13];
    const float* W2     = (const float*)d_in[14];
    const float* bm2    = (const float*)d_in[15];

    float* x = (float*)d_out;

    float *ln, *q, *k, *v, *sc, *hid;
    cudaGetSymbolAddress((void**)&ln,  g_ln);
    cudaGetSymbolAddress((void**)&q,   g_q);
    cudaGetSymbolAddress((void**)&k,   g_k);
    cudaGetSymbolAddress((void**)&v,   g_v);
    cudaGetSymbolAddress((void**)&sc,  g_sc);
    cudaGetSymbolAddress((void**)&hid, g_hid);

    cudaFuncSetAttribute(tc_gemm<false, false>,
                         cudaFuncAttributeMaxDynamicSharedMemorySize, TC_SMEM);
    cudaFuncSetAttribute(tc_gemm<true, false>,
                         cudaFuncAttributeMaxDynamicSharedMemorySize, TC_SMEM);
    cudaFuncSetAttribute(tc_gemm<false, true>,
                         cudaFuncAttributeMaxDynamicSharedMemorySize, TC_SMEM);

    const long long TD = (long long)SEQ * D_MODEL;
    const long long SS = (long long)SEQ * SEQ;
    const float inv_sqrt_d = 0.03125f;

    embed_kernel<<<NTOK, 256>>>(tokens, emb, x);

    for (int l = 0; l < NLAYERS; l++) {
        const float* wq = Wq + (size_t)l * D_MODEL * D_MODEL;
        const float* wk = Wk + (size_t)l * D_MODEL * D_MODEL;
        const float* wv = Wv + (size_t)l * D_MODEL * D_MODEL;
        const float* w1 = W1 + (size_t)l * D_MODEL * DFF;
        const float* w2 = W2 + (size_t)l * DFF * D_MODEL;

        ln_kernel<<<NTOK, 256>>>(x, g1 + l * D_MODEL, beta1 + l * D_MODEL, ln);

        dim3 gQKV(D_MODEL / 128, NTOK / 128, 1);
        tc_gemm<false, false><<<gQKV, 256, TC_SMEM>>>(
            ln, wq, q, bq + l * D_MODEL, nullptr,
            NTOK, D_MODEL, D_MODEL, 1.f, 0, 0, 0);
        tc_gemm<false, false><<<gQKV, 256, TC_SMEM>>>(
            ln, wk, k, bk + l * D_MODEL, nullptr,
            NTOK, D_MODEL, D_MODEL, 1.f, 0, 0, 0);
        tc_gemm<false, false><<<gQKV, 256, TC_SMEM>>>(
            ln, wv, v, bv + l * D_MODEL, nullptr,
            NTOK, D_MODEL, D_MODEL, 1.f, 0, 0, 0);

        dim3 gSC(SEQ / 128, SEQ / 128, BATCH);
        tc_gemm<true, false><<<gSC, 256, TC_SMEM>>>(
            q, k, sc, nullptr, nullptr,
            SEQ, SEQ, D_MODEL, inv_sqrt_d, TD, TD, SS);

        softmax_kernel<<<BATCH * SEQ, 256>>>(sc);

        dim3 gAV(D_MODEL / 128, SEQ / 128, BATCH);
        tc_gemm<false, false><<<gAV, 256, TC_SMEM>>>(
            sc, v, x, nullptr, x,
            SEQ, D_MODEL, SEQ, 1.f, SS, TD, TD);

        ln_kernel<<<NTOK, 256>>>(x, g2 + l * D_MODEL, beta2 + l * D_MODEL, ln);

        dim3 gM1(DFF / 128, NTOK / 128, 1);
        tc_gemm<false, true><<<gM1, 256, TC_SMEM>>>(
            ln, w1, hid, bm1 + l * DFF, nullptr,
            NTOK, DFF, D_MODEL, 1.f, 0, 0, 0);

        dim3 gM2(D_MODEL / 128, NTOK / 128, 1);
        tc_gemm<false, false><<<gM2, 256, TC_SMEM>>>(
            hid, w2, x, bm2 + l * D_MODEL, x,
            NTOK, D_MODEL, DFF, 1.f, 0, 0, 0);
    }
}

// round 4
// speedup vs baseline: 2.6577x; 1.3222x over previous
#include <cuda_runtime.h>
#include <cuda_bf16.h>
#include <math.h>
#include <stdint.h>

// ---------------------------------------------------------------------------
// Problem constants
// ---------------------------------------------------------------------------
#define D_MODEL 1024
#define DFF     4096
#define NLAYERS 8
#define BATCH   4
#define SEQ     2048
#define NTOK    (BATCH * SEQ)      // 8192
#define EPS     1e-5f

// ---------------------------------------------------------------------------
// Device scratch (allocation-free rule: __device__ globals)
// ---------------------------------------------------------------------------
__device__ float g_ln [NTOK * D_MODEL];
__device__ float g_q  [NTOK * D_MODEL];
__device__ float g_k  [NTOK * D_MODEL];
__device__ float g_v  [NTOK * D_MODEL];
__device__ float g_sc [BATCH * SEQ * SEQ];
__device__ float g_hid[NTOK * DFF];

// ---------------------------------------------------------------------------
// PTX helpers
// ---------------------------------------------------------------------------
__device__ __forceinline__ uint32_t smem_u32(const void* p) {
    uint32_t a;
    asm("{ .reg .u64 t; cvta.to.shared.u64 t, %1; cvt.u32.u64 %0, t; }"
        : "=r"(a) : "l"(p));
    return a;
}

__device__ __forceinline__ void ldsm_x4(uint32_t* r, uint32_t addr) {
    asm volatile("ldmatrix.sync.aligned.m8n8.x4.shared.b16 {%0,%1,%2,%3}, [%4];"
                 : "=r"(r[0]), "=r"(r[1]), "=r"(r[2]), "=r"(r[3]) : "r"(addr));
}

__device__ __forceinline__ void ldsm_x4_t(uint32_t* r, uint32_t addr) {
    asm volatile("ldmatrix.sync.aligned.m8n8.x4.trans.shared.b16 {%0,%1,%2,%3}, [%4];"
                 : "=r"(r[0]), "=r"(r[1]), "=r"(r[2]), "=r"(r[3]) : "r"(addr));
}

__device__ __forceinline__ void mma_bf16(float* c, const uint32_t* a, const uint32_t* b) {
    asm volatile(
        "mma.sync.aligned.m16n8k16.row.col.f32.bf16.bf16.f32 "
        "{%0,%1,%2,%3}, {%4,%5,%6,%7}, {%8,%9}, {%0,%1,%2,%3};"
        : "+f"(c[0]), "+f"(c[1]), "+f"(c[2]), "+f"(c[3])
        : "r"(a[0]), "r"(a[1]), "r"(a[2]), "r"(a[3]), "r"(b[0]), "r"(b[1]));
}

__device__ __forceinline__ void sts_v2(uint32_t addr, uint32_t a, uint32_t b) {
    asm volatile("st.shared.v2.b32 [%0], {%1, %2};" :: "r"(addr), "r"(a), "r"(b) : "memory");
}

__device__ __forceinline__ void cp_async16(uint32_t saddr, const void* gptr) {
    asm volatile("cp.async.cg.shared.global [%0], [%1], 16;"
                 :: "r"(saddr), "l"(gptr) : "memory");
}

__device__ __forceinline__ void cp_commit() {
    asm volatile("cp.async.commit_group;" ::: "memory");
}

__device__ __forceinline__ void cp_wait_all() {
    asm volatile("cp.async.wait_group 0;" ::: "memory");
}

// pack 4 floats into hi-bf16 pair and lo-bf16 pair
__device__ __forceinline__ void split4(const float4 v, uint32_t* hi, uint32_t* lo) {
    __nv_bfloat16 h0 = __float2bfloat16(v.x);
    __nv_bfloat16 h1 = __float2bfloat16(v.y);
    __nv_bfloat16 h2 = __float2bfloat16(v.z);
    __nv_bfloat16 h3 = __float2bfloat16(v.w);
    __nv_bfloat16 l0 = __float2bfloat16(v.x - __bfloat162float(h0));
    __nv_bfloat16 l1 = __float2bfloat16(v.y - __bfloat162float(h1));
    __nv_bfloat16 l2 = __float2bfloat16(v.z - __bfloat162float(h2));
    __nv_bfloat16 l3 = __float2bfloat16(v.w - __bfloat162float(h3));
    hi[0] = ((uint32_t)__bfloat16_as_ushort(h1) << 16) | __bfloat16_as_ushort(h0);
    hi[1] = ((uint32_t)__bfloat16_as_ushort(h3) << 16) | __bfloat16_as_ushort(h2);
    lo[0] = ((uint32_t)__bfloat16_as_ushort(l1) << 16) | __bfloat16_as_ushort(l0);
    lo[1] = ((uint32_t)__bfloat16_as_ushort(l3) << 16) | __bfloat16_as_ushort(l2);
}

// ---------------------------------------------------------------------------
// Elementwise kernels
// ---------------------------------------------------------------------------
__global__ __launch_bounds__(256)
void embed_kernel(const int* __restrict__ tokens,
                  const float* __restrict__ emb,
                  float* __restrict__ out)
{
    int row = blockIdx.x;
    int s   = row & (SEQ - 1);
    int tok = tokens[row];
    int d   = threadIdx.x * 4;

    float4 e = *(const float4*)&emb[(size_t)tok * D_MODEL + d];
    float o[4] = { e.x, e.y, e.z, e.w };
#pragma unroll
    for (int i = 0; i < 4; i++) {
        int dd = d + i;
        float freq = expf((float)(dd & ~1) * (-9.210340371976184f / (float)D_MODEL));
        float a = (float)s * freq;
        o[i] += (dd & 1) ? cosf(a) : sinf(a);
    }
    *(float4*)&out[(size_t)row * D_MODEL + d] = make_float4(o[0], o[1], o[2], o[3]);
}

__global__ __launch_bounds__(256)
void ln_kernel(const float* __restrict__ x,
               const float* __restrict__ g,
               const float* __restrict__ b,
               float* __restrict__ out)
{
    __shared__ float red[8];
    __shared__ float s_stat;

    int row = blockIdx.x;
    int tid = threadIdx.x;
    const float4* xr = (const float4*)(x + (size_t)row * D_MODEL);
    float4 v = xr[tid];

    float s = v.x + v.y + v.z + v.w;
#pragma unroll
    for (int o = 16; o > 0; o >>= 1) s += __shfl_xor_sync(0xffffffffu, s, o);
    if ((tid & 31) == 0) red[tid >> 5] = s;
    __syncthreads();
    if (tid == 0) {
        float t = 0.f;
#pragma unroll
        for (int i = 0; i < 8; i++) t += red[i];
        s_stat = t * (1.0f / D_MODEL);
    }
    __syncthreads();
    float mean = s_stat;

    float4 d;
    d.x = v.x - mean; d.y = v.y - mean; d.z = v.z - mean; d.w = v.w - mean;

    float s2 = d.x * d.x + d.y * d.y + d.z * d.z + d.w * d.w;
#pragma unroll
    for (int o = 16; o > 0; o >>= 1) s2 += __shfl_xor_sync(0xffffffffu, s2, o);
    if ((tid & 31) == 0) red[tid >> 5] = s2;
    __syncthreads();
    if (tid == 0) {
        float t = 0.f;
#pragma unroll
        for (int i = 0; i < 8; i++) t += red[i];
        s_stat = rsqrtf(t * (1.0f / D_MODEL) + EPS);
    }
    __syncthreads();
    float rstd = s_stat;

    float4 gg = *(const float4*)&g[tid * 4];
    float4 bb = *(const float4*)&b[tid * 4];
    float4 o4;
    o4.x = d.x * rstd * gg.x + bb.x;
    o4.y = d.y * rstd * gg.y + bb.y;
    o4.z = d.z * rstd * gg.z + bb.z;
    o4.w = d.w * rstd * gg.w + bb.w;
    *(float4*)(out + (size_t)row * D_MODEL + tid * 4) = o4;
}

__global__ __launch_bounds__(256)
void softmax_kernel(float* __restrict__ sc)
{
    __shared__ float red[8];
    __shared__ float s_val;

    size_t row = blockIdx.x;
    float4* p = (float4*)(sc + row * SEQ);
    int tid = threadIdx.x;

    float4 v0 = p[tid];
    float4 v1 = p[tid + 256];

    float m = fmaxf(fmaxf(fmaxf(v0.x, v0.y), fmaxf(v0.z, v0.w)),
                    fmaxf(fmaxf(v1.x, v1.y), fmaxf(v1.z, v1.w)));
#pragma unroll
    for (int o = 16; o > 0; o >>= 1) m = fmaxf(m, __shfl_xor_sync(0xffffffffu, m, o));
    if ((tid & 31) == 0) red[tid >> 5] = m;
    __syncthreads();
    if (tid == 0) {
        float t = red[0];
#pragma unroll
        for (int i = 1; i < 8; i++) t = fmaxf(t, red[i]);
        s_val = t;
    }
    __syncthreads();
    m = s_val;

    v0.x = expf(v0.x - m); v0.y = expf(v0.y - m);
    v0.z = expf(v0.z - m); v0.w = expf(v0.w - m);
    v1.x = expf(v1.x - m); v1.y = expf(v1.y - m);
    v1.z = expf(v1.z - m); v1.w = expf(v1.w - m);

    float s = v0.x + v0.y + v0.z + v0.w + v1.x + v1.y + v1.z + v1.w;
#pragma unroll
    for (int o = 16; o > 0; o >>= 1) s += __shfl_xor_sync(0xffffffffu, s, o);
    if ((tid & 31) == 0) red[tid >> 5] = s;
    __syncthreads();
    if (tid == 0) {
        float t = 0.f;
#pragma unroll
        for (int i = 0; i < 8; i++) t += red[i];
        s_val = t;
    }
    __syncthreads();
    float inv = 1.0f / s_val;

    v0.x *= inv; v0.y *= inv; v0.z *= inv; v0.w *= inv;
    v1.x *= inv; v1.y *= inv; v1.z *= inv; v1.w *= inv;
    p[tid]       = v0;
    p[tid + 256] = v1;
}

// ---------------------------------------------------------------------------
// Split-bf16 warp-MMA GEMM, 2 CTAs/SM.
// C = alpha * A @ op(B) (+bias) (relu) (+residual)
// cp.async fp32 staging (double-buffered 2x32KB) -> convert -> bf16 smem
// (single-buffered hi/lo) -> ldmatrix -> m16n8k16 bf16 MMA x3 split passes.
// Per k-step the 3 split passes each issue 16 independent MMAs.
// ---------------------------------------------------------------------------
#define A_STRIDE_B   80          // bytes per A/B-NT bf16 row (40 bf16)
#define A_BYTES      10240       // 128 * 80
#define BNN_STRIDE_B 272         // bytes per B-NN bf16 row (136 bf16)
#define STG_TILE     16384       // fp32 staging tile (128x32 or 32x128 floats)
#define STG_STAGE    32768       // A + B staging per stage
#define BF16_BASE    65536       // after 2 staging stages
#define TC_SMEM      (BF16_BASE + 40960)   // 106496 bytes -> 2 CTAs/SM

template<bool TRANSB, bool RELU>
__global__ __launch_bounds__(256, 2)
void tc_gemm(const float* __restrict__ A,
             const float* __restrict__ B,
             float* __restrict__ C,
             const float* __restrict__ bias,
             const float* __restrict__ residual,
             int M, int N, int K, float alpha,
             long long strA, long long strB, long long strC)
{
    extern __shared__ char smem[];
    const uint32_t sb = smem_u32(smem);
    const int tid  = threadIdx.x;
    const int wid  = tid >> 5;
    const int lane = tid & 31;
    const int wm   = wid >> 1;
    const int wn   = wid & 1;

    long long bz = blockIdx.z;
    A += bz * strA;
    B += bz * strB;
    C += bz * strC;
    const float* Rres = residual ? residual + bz * strC : nullptr;

    const int rowBase = blockIdx.y * 128;
    const int colBase = blockIdx.x * 128;

    const uint32_t aH = sb + BF16_BASE;
    const uint32_t aL = aH + A_BYTES;
    const uint32_t bH = aH + 2 * A_BYTES;
    const uint32_t bL = bH + (TRANSB ? A_BYTES : 8704);

    float acc[2][8][4];
#pragma unroll
    for (int i = 0; i < 2; i++)
#pragma unroll
        for (int j = 0; j < 8; j++)
#pragma unroll
            for (int t = 0; t < 4; t++) acc[i][j][t] = 0.f;

    const int nch = K >> 5;

    // thread's fixed staging coordinates
    const int ar = tid >> 3;           // A row (0..31 per i-step adds 32)
    const int ac = (tid & 7) << 2;     // A col (float)
    const int br = TRANSB ? (tid >> 3) : (tid >> 5);
    const int bc = TRANSB ? ((tid & 7) << 2) : ((tid & 31) << 2);

    // ---- prolog: cp.async chunk 0 into stage 0
    {
        const uint32_t stg = sb;
        const float* Ap = A + (size_t)rowBase * K;
#pragma unroll
        for (int i = 0; i < 4; i++) {
            int r = ar + i * 32;
            cp_async16(stg + (uint32_t)(r * 128 + ac * 4),
                       Ap + (size_t)r * K + ac);
        }
        if (TRANSB) {
            const float* Bp = B + (size_t)colBase * K;
#pragma unroll
            for (int i = 0; i < 4; i++) {
                int r = br + i * 32;
                cp_async16(stg + STG_TILE + (uint32_t)(r * 128 + bc * 4),
                           Bp + (size_t)r * K + bc);
            }
        } else {
            const float* Bp = B + colBase;
#pragma unroll
            for (int i = 0; i < 4; i++) {
                int r = br + i * 8;
                cp_async16(stg + STG_TILE + (uint32_t)(r * 512 + bc * 4),
                           Bp + (size_t)r * N + bc);
            }
        }
        cp_commit();
    }

    for (int c = 0; c < nch; c++) {
        const uint32_t stg = sb + (uint32_t)(c & 1) * STG_STAGE;

        cp_wait_all();
        __syncthreads();   // staging ready everywhere; bf16 bufs consumed

        // ---- convert staging fp32 -> bf16 hi/lo smem
#pragma unroll
        for (int i = 0; i < 4; i++) {
            int r = ar + i * 32;
            float4 v = *(const float4*)(smem + (stg - sb) + r * 128 + ac * 4);
            uint32_t hi[2], lo[2];
            split4(v, hi, lo);
            uint32_t off = (uint32_t)r * A_STRIDE_B + ((uint32_t)(tid & 7) << 3);
            sts_v2(aH + off, hi[0], hi[1]);
            sts_v2(aL + off, lo[0], lo[1]);
        }
        if (TRANSB) {
#pragma unroll
            for (int i = 0; i < 4; i++) {
                int r = br + i * 32;
                float4 v = *(const float4*)(smem + (stg - sb) + STG_TILE + r * 128 + bc * 4);
                uint32_t hi[2], lo[2];
                split4(v, hi, lo);
                uint32_t off = (uint32_t)r * A_STRIDE_B + ((uint32_t)(tid & 7) << 3);
                sts_v2(bH + off, hi[0], hi[1]);
                sts_v2(bL + off, lo[0], lo[1]);
            }
        } else {
#pragma unroll
            for (int i = 0; i < 4; i++) {
                int r = br + i * 8;
                float4 v = *(const float4*)(smem + (stg - sb) + STG_TILE + r * 512 + bc * 4);
                uint32_t hi[2], lo[2];
                split4(v, hi, lo);
                uint32_t off = (uint32_t)r * BNN_STRIDE_B + ((uint32_t)(tid & 31) << 3);
                sts_v2(bH + off, hi[0], hi[1]);
                sts_v2(bL + off, lo[0], lo[1]);
            }
        }

        // ---- cp.async next chunk into other stage
        if (c + 1 < nch) {
            const uint32_t nst = sb + (uint32_t)((c + 1) & 1) * STG_STAGE;
            const float* Ap = A + (size_t)rowBase * K + (size_t)(c + 1) * 32;
#pragma unroll
            for (int i = 0; i < 4; i++) {
                int r = ar + i * 32;
                cp_async16(nst + (uint32_t)(r * 128 + ac * 4),
                           Ap + (size_t)r * K + ac);
            }
            if (TRANSB) {
                const float* Bp = B + (size_t)colBase * K + (size_t)(c + 1) * 32;
#pragma unroll
                for (int i = 0; i < 4; i++) {
                    int r = br + i * 32;
                    cp_async16(nst + STG_TILE + (uint32_t)(r * 128 + bc * 4),
                               Bp + (size_t)r * K + bc);
                }
            } else {
                const float* Bp = B + (size_t)((c + 1) * 32) * N + colBase;
#pragma unroll
                for (int i = 0; i < 4; i++) {
                    int r = br + i * 8;
                    cp_async16(nst + STG_TILE + (uint32_t)(r * 512 + bc * 4),
                               Bp + (size_t)r * N + bc);
                }
            }
            cp_commit();
        }

        __syncthreads();   // bf16 bufs ready

        // ---- compute: 2 k16 steps; per step 3 split passes of 16 indep MMAs
#pragma unroll
        for (int ks = 0; ks < 2; ks++) {
            uint32_t ah[2][4], al[2][4];
#pragma unroll
            for (int mt = 0; mt < 2; mt++) {
                uint32_t off = (uint32_t)(wm * 32 + mt * 16 + (lane & 15)) * A_STRIDE_B
                             + (uint32_t)(ks * 16 + (lane >> 4) * 8) * 2;
                ldsm_x4(ah[mt], aH + off);
                ldsm_x4(al[mt], aL + off);
            }
#pragma unroll
            for (int s = 0; s < 3; s++) {
                const uint32_t bbase = (s == 1) ? bL : bH;
#pragma unroll
                for (int p = 0; p < 4; p++) {
                    uint32_t bf[4];
                    if (TRANSB) {
                        uint32_t off = (uint32_t)(wn * 64 + p * 16 + (lane & 7) + ((lane >> 4) & 1) * 8) * A_STRIDE_B
                                     + (uint32_t)(ks * 16 + ((lane >> 3) & 1) * 8) * 2;
                        ldsm_x4(bf, bbase + off);
                    } else {
                        uint32_t off = (uint32_t)(ks * 16 + (lane & 7) + ((lane >> 3) & 1) * 8) * BNN_STRIDE_B
                                     + (uint32_t)(wn * 64 + p * 16 + (lane >> 4) * 8) * 2;
                        ldsm_x4_t(bf, bbase + off);
                    }
#pragma unroll
                    for (int mt = 0; mt < 2; mt++) {
                        const uint32_t* af = (s == 2) ? al[mt] : ah[mt];
#pragma unroll
                        for (int g = 0; g < 2; g++)
                            mma_bf16(acc[mt][p * 2 + g], af, bf + 2 * g);
                    }
                }
            }
        }
        __syncthreads();
    }

    // ---- epilogue
#pragma unroll
    for (int mt = 0; mt < 2; mt++) {
        int r0 = rowBase + wm * 32 + mt * 16 + (lane >> 2);
#pragma unroll
        for (int ng = 0; ng < 8; ng++) {
            int col = colBase + wn * 64 + ng * 8 + (lane & 3) * 2;
            float2 v0, v1;
            v0.x = alpha * acc[mt][ng][0];
            v0.y = alpha * acc[mt][ng][1];
            v1.x = alpha * acc[mt][ng][2];
            v1.y = alpha * acc[mt][ng][3];
            if (bias) {
                float2 bb = *(const float2*)&bias[col];
                v0.x += bb.x; v0.y += bb.y;
                v1.x += bb.x; v1.y += bb.y;
            }
            if (RELU) {
                v0.x = fmaxf(v0.x, 0.f); v0.y = fmaxf(v0.y, 0.f);
                v1.x = fmaxf(v1.x, 0.f); v1.y = fmaxf(v1.y, 0.f);
            }
            if (Rres) {
                float2 q0 = *(const float2*)&Rres[(size_t)r0 * N + col];
                float2 q1 = *(const float2*)&Rres[(size_t)(r0 + 8) * N + col];
                v0.x += q0.x; v0.y += q0.y;
                v1.x += q1.x; v1.y += q1.y;
            }
            *(float2*)&C[(size_t)r0 * N + col]       = v0;
            *(float2*)&C[(size_t)(r0 + 8) * N + col] = v1;
        }
    }
}

// ---------------------------------------------------------------------------
// Host launcher
// ---------------------------------------------------------------------------
extern "C" void kernel_launch(void* const* d_in, const int* in_sizes, int n_in,
                              void* d_out, int out_size)
{
    const int*   tokens = (const int*)  d_in[0];
    const float* emb    = (const float*)d_in[1];
    const float* Wq     = (const float*)d_in[2];
    const float* bq     = (const float*)d_in[3];
    const float* Wk     = (const float*)d_in[4];
    const float* bk     = (const float*)d_in[5];
    const float* Wv     = (const float*)d_in[6];
    const float* bv     = (const float*)d_in[7];
    const float* g1     = (const float*)d_in[8];
    const float* beta1  = (const float*)d_in[9];
    const float* g2     = (const float*)d_in[10];
    const float* beta2  = (const float*)d_in[11];
    const float* W1     = (const float*)d_in[12];
    const float* bm1    = (const float*)d_in[13];
    const float* W2     = (const float*)d_in[14];
    const float* bm2    = (const float*)d_in[15];

    float* x = (float*)d_out;

    float *ln, *q, *k, *v, *sc, *hid;
    cudaGetSymbolAddress((void**)&ln,  g_ln);
    cudaGetSymbolAddress((void**)&q,   g_q);
    cudaGetSymbolAddress((void**)&k,   g_k);
    cudaGetSymbolAddress((void**)&v,   g_v);
    cudaGetSymbolAddress((void**)&sc,  g_sc);
    cudaGetSymbolAddress((void**)&hid, g_hid);

    cudaFuncSetAttribute(tc_gemm<false, false>,
                         cudaFuncAttributeMaxDynamicSharedMemorySize, TC_SMEM);
    cudaFuncSetAttribute(tc_gemm<true, false>,
                         cudaFuncAttributeMaxDynamicSharedMemorySize, TC_SMEM);
    cudaFuncSetAttribute(tc_gemm<false, true>,
                         cudaFuncAttributeMaxDynamicSharedMemorySize, TC_SMEM);

    const long long TD = (long long)SEQ * D_MODEL;
    const long long SS = (long long)SEQ * SEQ;
    const float inv_sqrt_d = 0.03125f;

    embed_kernel<<<NTOK, 256>>>(tokens, emb, x);

    for (int l = 0; l < NLAYERS; l++) {
        const float* wq = Wq + (size_t)l * D_MODEL * D_MODEL;
        const float* wk = Wk + (size_t)l * D_MODEL * D_MODEL;
        const float* wv = Wv + (size_t)l * D_MODEL * D_MODEL;
        const float* w1 = W1 + (size_t)l * D_MODEL * DFF;
        const float* w2 = W2 + (size_t)l * DFF * D_MODEL;

        ln_kernel<<<NTOK, 256>>>(x, g1 + l * D_MODEL, beta1 + l * D_MODEL, ln);

        dim3 gQKV(D_MODEL / 128, NTOK / 128, 1);
        tc_gemm<false, false><<<gQKV, 256, TC_SMEM>>>(
            ln, wq, q, bq + l * D_MODEL, nullptr,
            NTOK, D_MODEL, D_MODEL, 1.f, 0, 0, 0);
        tc_gemm<false, false><<<gQKV, 256, TC_SMEM>>>(
            ln, wk, k, bk + l * D_MODEL, nullptr,
            NTOK, D_MODEL, D_MODEL, 1.f, 0, 0, 0);
        tc_gemm<false, false><<<gQKV, 256, TC_SMEM>>>(
            ln, wv, v, bv + l * D_MODEL, nullptr,
            NTOK, D_MODEL, D_MODEL, 1.f, 0, 0, 0);

        dim3 gSC(SEQ / 128, SEQ / 128, BATCH);
        tc_gemm<true, false><<<gSC, 256, TC_SMEM>>>(
            q, k, sc, nullptr, nullptr,
            SEQ, SEQ, D_MODEL, inv_sqrt_d, TD, TD, SS);

        softmax_kernel<<<BATCH * SEQ, 256>>>(sc);

        dim3 gAV(D_MODEL / 128, SEQ / 128, BATCH);
        tc_gemm<false, false><<<gAV, 256, TC_SMEM>>>(
            sc, v, x, nullptr, x,
            SEQ, D_MODEL, SEQ, 1.f, SS, TD, TD);

        ln_kernel<<<NTOK, 256>>>(x, g2 + l * D_MODEL, beta2 + l * D_MODEL, ln);

        dim3 gM1(DFF / 128, NTOK / 128, 1);
        tc_gemm<false, true><<<gM1, 256, TC_SMEM>>>(
            ln, w1, hid, bm1 + l * DFF, nullptr,
            NTOK, DFF, D_MODEL, 1.f, 0, 0, 0);

        dim3 gM2(D_MODEL / 128, NTOK / 128, 1);
        tc_gemm<false, false><<<gM2, 256, TC_SMEM>>>(
            hid, w2, x, bm2 + l * D_MODEL, x,
            NTOK, D_MODEL, DFF, 1.f, 0, 0, 0);
    }
}

// round 5
// speedup vs baseline: 2.8617x; 1.0768x over previous
#include <cuda_runtime.h>
#include <cuda_bf16.h>
#include <math.h>
#include <stdint.h>

// ---------------------------------------------------------------------------
// Problem constants
// ---------------------------------------------------------------------------
#define D_MODEL 1024
#define DFF     4096
#define NLAYERS 8
#define BATCH   4
#define SEQ     2048
#define NTOK    (BATCH * SEQ)      // 8192
#define EPS     1e-5f

typedef __nv_bfloat16 bf16;

// ---------------------------------------------------------------------------
// Device scratch (allocation-free rule: __device__ globals)
// ---------------------------------------------------------------------------
__device__ bf16  g_lnH [NTOK * D_MODEL];
__device__ bf16  g_lnL [NTOK * D_MODEL];
__device__ bf16  g_qH  [NTOK * D_MODEL];
__device__ bf16  g_qL  [NTOK * D_MODEL];
__device__ bf16  g_kH  [NTOK * D_MODEL];
__device__ bf16  g_kL  [NTOK * D_MODEL];
__device__ bf16  g_vH  [NTOK * D_MODEL];
__device__ bf16  g_vL  [NTOK * D_MODEL];
__device__ float g_sc  [BATCH * SEQ * SEQ];
__device__ bf16  g_scH [BATCH * SEQ * SEQ];
__device__ bf16  g_scL [BATCH * SEQ * SEQ];
__device__ bf16  g_hidH[NTOK * DFF];
__device__ bf16  g_hidL[NTOK * DFF];
// pre-split weights
__device__ bf16  g_WqH[NLAYERS * D_MODEL * D_MODEL];
__device__ bf16  g_WqL[NLAYERS * D_MODEL * D_MODEL];
__device__ bf16  g_WkH[NLAYERS * D_MODEL * D_MODEL];
__device__ bf16  g_WkL[NLAYERS * D_MODEL * D_MODEL];
__device__ bf16  g_WvH[NLAYERS * D_MODEL * D_MODEL];
__device__ bf16  g_WvL[NLAYERS * D_MODEL * D_MODEL];
__device__ bf16  g_W1H[NLAYERS * D_MODEL * DFF];
__device__ bf16  g_W1L[NLAYERS * D_MODEL * DFF];
__device__ bf16  g_W2H[NLAYERS * DFF * D_MODEL];
__device__ bf16  g_W2L[NLAYERS * DFF * D_MODEL];

// ---------------------------------------------------------------------------
// PTX helpers
// ---------------------------------------------------------------------------
__device__ __forceinline__ uint32_t smem_u32(const void* p) {
    uint32_t a;
    asm("{ .reg .u64 t; cvta.to.shared.u64 t, %1; cvt.u32.u64 %0, t; }"
        : "=r"(a) : "l"(p));
    return a;
}

__device__ __forceinline__ void ldsm_x4(uint32_t* r, uint32_t addr) {
    asm volatile("ldmatrix.sync.aligned.m8n8.x4.shared.b16 {%0,%1,%2,%3}, [%4];"
                 : "=r"(r[0]), "=r"(r[1]), "=r"(r[2]), "=r"(r[3]) : "r"(addr));
}

__device__ __forceinline__ void ldsm_x4_t(uint32_t* r, uint32_t addr) {
    asm volatile("ldmatrix.sync.aligned.m8n8.x4.trans.shared.b16 {%0,%1,%2,%3}, [%4];"
                 : "=r"(r[0]), "=r"(r[1]), "=r"(r[2]), "=r"(r[3]) : "r"(addr));
}

__device__ __forceinline__ void mma_bf16(float* c, const uint32_t* a, const uint32_t* b) {
    asm volatile(
        "mma.sync.aligned.m16n8k16.row.col.f32.bf16.bf16.f32 "
        "{%0,%1,%2,%3}, {%4,%5,%6,%7}, {%8,%9}, {%0,%1,%2,%3};"
        : "+f"(c[0]), "+f"(c[1]), "+f"(c[2]), "+f"(c[3])
        : "r"(a[0]), "r"(a[1]), "r"(a[2]), "r"(a[3]), "r"(b[0]), "r"(b[1]));
}

__device__ __forceinline__ void cp_async16(uint32_t saddr, const void* gptr) {
    asm volatile("cp.async.cg.shared.global [%0], [%1], 16;"
                 :: "r"(saddr), "l"(gptr) : "memory");
}
__device__ __forceinline__ void cp_commit() {
    asm volatile("cp.async.commit_group;" ::: "memory");
}
__device__ __forceinline__ void cp_wait_all() {
    asm volatile("cp.async.wait_group 0;" ::: "memory");
}

__device__ __forceinline__ uint32_t pack2(bf16 a, bf16 b) {
    return ((uint32_t)__bfloat16_as_ushort(b) << 16) | __bfloat16_as_ushort(a);
}

// split 4 floats -> hi pair-of-u32, lo pair-of-u32
__device__ __forceinline__ void split4(const float4 v, uint32_t* hi, uint32_t* lo) {
    bf16 h0 = __float2bfloat16(v.x);
    bf16 h1 = __float2bfloat16(v.y);
    bf16 h2 = __float2bfloat16(v.z);
    bf16 h3 = __float2bfloat16(v.w);
    hi[0] = pack2(h0, h1);
    hi[1] = pack2(h2, h3);
    lo[0] = pack2(__float2bfloat16(v.x - __bfloat162float(h0)),
                  __float2bfloat16(v.y - __bfloat162float(h1)));
    lo[1] = pack2(__float2bfloat16(v.z - __bfloat162float(h2)),
                  __float2bfloat16(v.w - __bfloat162float(h3)));
}

// ---------------------------------------------------------------------------
// Weight pre-split kernel: fp32 -> (hi, lo) bf16
// ---------------------------------------------------------------------------
__global__ __launch_bounds__(256)
void split_kernel(const float* __restrict__ in,
                  bf16* __restrict__ oh, bf16* __restrict__ ol, int n4)
{
    int i = blockIdx.x * 256 + threadIdx.x;
    if (i >= n4) return;
    float4 v = ((const float4*)in)[i];
    uint32_t hi[2], lo[2];
    split4(v, hi, lo);
    ((uint2*)oh)[i] = make_uint2(hi[0], hi[1]);
    ((uint2*)ol)[i] = make_uint2(lo[0], lo[1]);
}

// ---------------------------------------------------------------------------
// Embedding + sinusoidal PE (fp32 residual stream)
// ---------------------------------------------------------------------------
__global__ __launch_bounds__(256)
void embed_kernel(const int* __restrict__ tokens,
                  const float* __restrict__ emb,
                  float* __restrict__ out)
{
    int row = blockIdx.x;
    int s   = row & (SEQ - 1);
    int tok = tokens[row];
    int d   = threadIdx.x * 4;

    float4 e = *(const float4*)&emb[(size_t)tok * D_MODEL + d];
    float o[4] = { e.x, e.y, e.z, e.w };
#pragma unroll
    for (int i = 0; i < 4; i++) {
        int dd = d + i;
        float freq = expf((float)(dd & ~1) * (-9.210340371976184f / (float)D_MODEL));
        float a = (float)s * freq;
        o[i] += (dd & 1) ? cosf(a) : sinf(a);
    }
    *(float4*)&out[(size_t)row * D_MODEL + d] = make_float4(o[0], o[1], o[2], o[3]);
}

// ---------------------------------------------------------------------------
// LayerNorm: fp32 in -> hi/lo bf16 out
// ---------------------------------------------------------------------------
__global__ __launch_bounds__(256)
void ln_kernel(const float* __restrict__ x,
               const float* __restrict__ g,
               const float* __restrict__ b,
               bf16* __restrict__ oh, bf16* __restrict__ ol)
{
    __shared__ float red[8];
    __shared__ float s_stat;

    int row = blockIdx.x;
    int tid = threadIdx.x;
    const float4* xr = (const float4*)(x + (size_t)row * D_MODEL);
    float4 v = xr[tid];

    float s = v.x + v.y + v.z + v.w;
#pragma unroll
    for (int o = 16; o > 0; o >>= 1) s += __shfl_xor_sync(0xffffffffu, s, o);
    if ((tid & 31) == 0) red[tid >> 5] = s;
    __syncthreads();
    if (tid == 0) {
        float t = 0.f;
#pragma unroll
        for (int i = 0; i < 8; i++) t += red[i];
        s_stat = t * (1.0f / D_MODEL);
    }
    __syncthreads();
    float mean = s_stat;

    float4 d;
    d.x = v.x - mean; d.y = v.y - mean; d.z = v.z - mean; d.w = v.w - mean;

    float s2 = d.x * d.x + d.y * d.y + d.z * d.z + d.w * d.w;
#pragma unroll
    for (int o = 16; o > 0; o >>= 1) s2 += __shfl_xor_sync(0xffffffffu, s2, o);
    if ((tid & 31) == 0) red[tid >> 5] = s2;
    __syncthreads();
    if (tid == 0) {
        float t = 0.f;
#pragma unroll
        for (int i = 0; i < 8; i++) t += red[i];
        s_stat = rsqrtf(t * (1.0f / D_MODEL) + EPS);
    }
    __syncthreads();
    float rstd = s_stat;

    float4 gg = *(const float4*)&g[tid * 4];
    float4 bb = *(const float4*)&b[tid * 4];
    float4 o4;
    o4.x = d.x * rstd * gg.x + bb.x;
    o4.y = d.y * rstd * gg.y + bb.y;
    o4.z = d.z * rstd * gg.z + bb.z;
    o4.w = d.w * rstd * gg.w + bb.w;

    uint32_t hi[2], lo[2];
    split4(o4, hi, lo);
    ((uint2*)(oh + (size_t)row * D_MODEL))[tid] = make_uint2(hi[0], hi[1]);
    ((uint2*)(ol + (size_t)row * D_MODEL))[tid] = make_uint2(lo[0], lo[1]);
}

// ---------------------------------------------------------------------------
// Softmax: fp32 in -> hi/lo bf16 out
// ---------------------------------------------------------------------------
__global__ __launch_bounds__(256)
void softmax_kernel(const float* __restrict__ sc,
                    bf16* __restrict__ oh, bf16* __restrict__ ol)
{
    __shared__ float red[8];
    __shared__ float s_val;

    size_t row = blockIdx.x;
    const float4* p = (const float4*)(sc + row * SEQ);
    int tid = threadIdx.x;

    float4 v0 = p[tid];
    float4 v1 = p[tid + 256];

    float m = fmaxf(fmaxf(fmaxf(v0.x, v0.y), fmaxf(v0.z, v0.w)),
                    fmaxf(fmaxf(v1.x, v1.y), fmaxf(v1.z, v1.w)));
#pragma unroll
    for (int o = 16; o > 0; o >>= 1) m = fmaxf(m, __shfl_xor_sync(0xffffffffu, m, o));
    if ((tid & 31) == 0) red[tid >> 5] = m;
    __syncthreads();
    if (tid == 0) {
        float t = red[0];
#pragma unroll
        for (int i = 1; i < 8; i++) t = fmaxf(t, red[i]);
        s_val = t;
    }
    __syncthreads();
    m = s_val;

    v0.x = expf(v0.x - m); v0.y = expf(v0.y - m);
    v0.z = expf(v0.z - m); v0.w = expf(v0.w - m);
    v1.x = expf(v1.x - m); v1.y = expf(v1.y - m);
    v1.z = expf(v1.z - m); v1.w = expf(v1.w - m);

    float s = v0.x + v0.y + v0.z + v0.w + v1.x + v1.y + v1.z + v1.w;
#pragma unroll
    for (int o = 16; o > 0; o >>= 1) s += __shfl_xor_sync(0xffffffffu, s, o);
    if ((tid & 31) == 0) red[tid >> 5] = s;
    __syncthreads();
    if (tid == 0) {
        float t = 0.f;
#pragma unroll
        for (int i = 0; i < 8; i++) t += red[i];
        s_val = t;
    }
    __syncthreads();
    float inv = 1.0f / s_val;

    v0.x *= inv; v0.y *= inv; v0.z *= inv; v0.w *= inv;
    v1.x *= inv; v1.y *= inv; v1.z *= inv; v1.w *= inv;

    uint32_t hi[2], lo[2];
    split4(v0, hi, lo);
    ((uint2*)(oh + row * SEQ))[tid] = make_uint2(hi[0], hi[1]);
    ((uint2*)(ol + row * SEQ))[tid] = make_uint2(lo[0], lo[1]);
    split4(v1, hi, lo);
    ((uint2*)(oh + row * SEQ))[tid + 256] = make_uint2(hi[0], hi[1]);
    ((uint2*)(ol + row * SEQ))[tid + 256] = make_uint2(lo[0], lo[1]);
}

// ---------------------------------------------------------------------------
// Pure-bf16 split-3 warp-MMA GEMM, 2 CTAs/SM.
// Operands pre-split into hi/lo bf16. cp.async direct into ldmatrix layout,
// double-buffered. 128x128 tile, BK=32, 8 warps (4M x 2N), 3 split passes.
// Outputs: fp32 (opt, +bias/relu/residual) and/or hi+lo bf16.
// ---------------------------------------------------------------------------
#define A_STRIDE_B   80          // bytes per K-major bf16 row (32 data + 8 pad)
#define A_TILE_B     10240       // 128 * 80
#define BNN_STRIDE_B 272         // bytes per NN bf16 row (128 data + 8 pad)
#define BNN_TILE_B   8704        // 32 * 272
#define STAGE_B      40960
#define TC_SMEM      (2 * STAGE_B)   // 81920 bytes -> 2 CTAs/SM

template<bool TRANSB>
__device__ __forceinline__ void load_chunk(
    uint32_t stg, const bf16* Ah, const bf16* Al,
    const bf16* Bh, const bf16* Bl,
    int rowBase, int colBase, int kb, int N, int K, int tid)
{
    const uint32_t aH = stg;
    const uint32_t aL = stg + A_TILE_B;
    const uint32_t bH = stg + 2 * A_TILE_B;
    const uint32_t bL = bH + (TRANSB ? A_TILE_B : BNN_TILE_B);

#pragma unroll
    for (int i = 0; i < 2; i++) {
        int id = tid + (i << 8);
        int r = id >> 2;
        int c8 = (id & 3) << 3;          // bf16 element offset (0,8,16,24)
        uint32_t so = (uint32_t)r * A_STRIDE_B + (uint32_t)(c8 << 1);
        size_t go = (size_t)(rowBase + r) * K + kb + c8;
        cp_async16(aH + so, Ah + go);
        cp_async16(aL + so, Al + go);
    }
    if (TRANSB) {
#pragma unroll
        for (int i = 0; i < 2; i++) {
            int id = tid + (i << 8);
            int r = id >> 2;
            int c8 = (id & 3) << 3;
            uint32_t so = (uint32_t)r * A_STRIDE_B + (uint32_t)(c8 << 1);
            size_t go = (size_t)(colBase + r) * K + kb + c8;
            cp_async16(bH + so, Bh + go);
            cp_async16(bL + so, Bl + go);
        }
    } else {
#pragma unroll
        for (int i = 0; i < 2; i++) {
            int id = tid + (i << 8);
            int r = id >> 4;                 // 0..31 (k row)
            int c8 = (id & 15) << 3;         // 0..120
            uint32_t so = (uint32_t)r * BNN_STRIDE_B + (uint32_t)(c8 << 1);
            size_t go = (size_t)(kb + r) * N + colBase + c8;
            cp_async16(bH + so, Bh + go);
            cp_async16(bL + so, Bl + go);
        }
    }
    cp_commit();
}

template<bool TRANSB, bool RELU, bool OF32, bool OB16>
__global__ __launch_bounds__(256, 2)
void tc_gemm(const bf16* __restrict__ Ah, const bf16* __restrict__ Al,
             const bf16* __restrict__ Bh, const bf16* __restrict__ Bl,
             float* __restrict__ Cf,
             bf16* __restrict__ Ch, bf16* __restrict__ Cl,
             const float* __restrict__ bias,
             const float* __restrict__ residual,
             int M, int N, int K, float alpha,
             long long strA, long long strB, long long strC)
{
    extern __shared__ char smem[];
    const uint32_t sb = smem_u32(smem);
    const int tid  = threadIdx.x;
    const int wid  = tid >> 5;
    const int lane = tid & 31;
    const int wm   = wid >> 1;
    const int wn   = wid & 1;

    long long bz = blockIdx.z;
    Ah += bz * strA; Al += bz * strA;
    Bh += bz * strB; Bl += bz * strB;
    if (OF32) Cf += bz * strC;
    const float* Rres = (OF32 && residual) ? residual + bz * strC : nullptr;

    const int rowBase = blockIdx.y * 128;
    const int colBase = blockIdx.x * 128;

    float acc[2][8][4];
#pragma unroll
    for (int i = 0; i < 2; i++)
#pragma unroll
        for (int j = 0; j < 8; j++)
#pragma unroll
            for (int t = 0; t < 4; t++) acc[i][j][t] = 0.f;

    const int nch = K >> 5;

    // prolog: chunk 0 into stage 0
    load_chunk<TRANSB>(sb, Ah, Al, Bh, Bl, rowBase, colBase, 0, N, K, tid);

    for (int c = 0; c < nch; c++) {
        const uint32_t stg = sb + (uint32_t)(c & 1) * STAGE_B;
        const uint32_t aH = stg;
        const uint32_t aL = stg + A_TILE_B;
        const uint32_t bH = stg + 2 * A_TILE_B;
        const uint32_t bL = bH + (TRANSB ? A_TILE_B : BNN_TILE_B);

        cp_wait_all();
        __syncthreads();

        if (c + 1 < nch)
            load_chunk<TRANSB>(sb + (uint32_t)((c + 1) & 1) * STAGE_B,
                               Ah, Al, Bh, Bl, rowBase, colBase,
                               (c + 1) * 32, N, K, tid);

        // compute: 2 k16 steps; per step 3 split passes of 16 indep MMAs
#pragma unroll
        for (int ks = 0; ks < 2; ks++) {
            uint32_t ah[2][4], al[2][4];
#pragma unroll
            for (int mt = 0; mt < 2; mt++) {
                uint32_t off = (uint32_t)(wm * 32 + mt * 16 + (lane & 15)) * A_STRIDE_B
                             + (uint32_t)(ks * 16 + (lane >> 4) * 8) * 2;
                ldsm_x4(ah[mt], aH + off);
                ldsm_x4(al[mt], aL + off);
            }
#pragma unroll
            for (int s = 0; s < 3; s++) {
                const uint32_t bbase = (s == 1) ? bL : bH;
#pragma unroll
                for (int p = 0; p < 4; p++) {
                    uint32_t bf[4];
                    if (TRANSB) {
                        uint32_t off = (uint32_t)(wn * 64 + p * 16 + (lane & 7) + ((lane >> 4) & 1) * 8) * A_STRIDE_B
                                     + (uint32_t)(ks * 16 + ((lane >> 3) & 1) * 8) * 2;
                        ldsm_x4(bf, bbase + off);
                    } else {
                        uint32_t off = (uint32_t)(ks * 16 + (lane & 7) + ((lane >> 3) & 1) * 8) * BNN_STRIDE_B
                                     + (uint32_t)(wn * 64 + p * 16 + (lane >> 4) * 8) * 2;
                        ldsm_x4_t(bf, bbase + off);
                    }
#pragma unroll
                    for (int mt = 0; mt < 2; mt++) {
                        const uint32_t* af = (s == 2) ? al[mt] : ah[mt];
#pragma unroll
                        for (int g = 0; g < 2; g++)
                            mma_bf16(acc[mt][p * 2 + g], af, bf + 2 * g);
                    }
                }
            }
        }
        __syncthreads();
    }

    // ---- epilogue
#pragma unroll
    for (int mt = 0; mt < 2; mt++) {
        int r0 = rowBase + wm * 32 + mt * 16 + (lane >> 2);
#pragma unroll
        for (int ng = 0; ng < 8; ng++) {
            int col = colBase + wn * 64 + ng * 8 + (lane & 3) * 2;
            float2 v0, v1;
            v0.x = alpha * acc[mt][ng][0];
            v0.y = alpha * acc[mt][ng][1];
            v1.x = alpha * acc[mt][ng][2];
            v1.y = alpha * acc[mt][ng][3];
            if (bias) {
                float2 bb = *(const float2*)&bias[col];
                v0.x += bb.x; v0.y += bb.y;
                v1.x += bb.x; v1.y += bb.y;
            }
            if (RELU) {
                v0.x = fmaxf(v0.x, 0.f); v0.y = fmaxf(v0.y, 0.f);
                v1.x = fmaxf(v1.x, 0.f); v1.y = fmaxf(v1.y, 0.f);
            }
            if (OF32) {
                float2 w0 = v0, w1 = v1;
                if (Rres) {
                    float2 q0 = *(const float2*)&Rres[(size_t)r0 * N + col];
                    float2 q1 = *(const float2*)&Rres[(size_t)(r0 + 8) * N + col];
                    w0.x += q0.x; w0.y += q0.y;
                    w1.x += q1.x; w1.y += q1.y;
                }
                *(float2*)&Cf[(size_t)r0 * N + col]       = w0;
                *(float2*)&Cf[(size_t)(r0 + 8) * N + col] = w1;
            }
            if (OB16) {
                bf16 h0 = __float2bfloat16(v0.x);
                bf16 h1 = __float2bfloat16(v0.y);
                bf16 h2 = __float2bfloat16(v1.x);
                bf16 h3 = __float2bfloat16(v1.y);
                *(uint32_t*)&Ch[(size_t)r0 * N + col] = pack2(h0, h1);
                *(uint32_t*)&Ch[(size_t)(r0 + 8) * N + col] = pack2(h2, h3);
                *(uint32_t*)&Cl[(size_t)r0 * N + col] =
                    pack2(__float2bfloat16(v0.x - __bfloat162float(h0)),
                          __float2bfloat16(v0.y - __bfloat162float(h1)));
                *(uint32_t*)&Cl[(size_t)(r0 + 8) * N + col] =
                    pack2(__float2bfloat16(v1.x - __bfloat162float(h2)),
                          __float2bfloat16(v1.y - __bfloat162float(h3)));
            }
        }
    }
}

// ---------------------------------------------------------------------------
// Host launcher
// ---------------------------------------------------------------------------
extern "C" void kernel_launch(void* const* d_in, const int* in_sizes, int n_in,
                              void* d_out, int out_size)
{
    const int*   tokens = (const int*)  d_in[0];
    const float* emb    = (const float*)d_in[1];
    const float* Wq     = (const float*)d_in[2];
    const float* bq     = (const float*)d_in[3];
    const float* Wk     = (const float*)d_in[4];
    const float* bk     = (const float*)d_in[5];
    const float* Wv     = (const float*)d_in[6];
    const float* bv     = (const float*)d_in[7];
    const float* g1     = (const float*)d_in[8];
    const float* beta1  = (const float*)d_in[9];
    const float* g2     = (const float*)d_in[10];
    const float* beta2  = (const float*)d_in[11];
    const float* W1     = (const float*)d_in[12];
    const float* bm1    = (const float*)d_in[13];
    const float* W2     = (const float*)d_in[14];
    const float* bm2    = (const float*)d_in[15];

    float* x = (float*)d_out;

    bf16 *lnH, *lnL, *qH, *qL, *kH, *kL, *vH, *vL, *scH, *scL, *hidH, *hidL;
    bf16 *WqH, *WqL, *WkH, *WkL, *WvH, *WvL, *W1H, *W1L, *W2H, *W2L;
    float* sc;
    cudaGetSymbolAddress((void**)&lnH,  g_lnH);
    cudaGetSymbolAddress((void**)&lnL,  g_lnL);
    cudaGetSymbolAddress((void**)&qH,   g_qH);
    cudaGetSymbolAddress((void**)&qL,   g_qL);
    cudaGetSymbolAddress((void**)&kH,   g_kH);
    cudaGetSymbolAddress((void**)&kL,   g_kL);
    cudaGetSymbolAddress((void**)&vH,   g_vH);
    cudaGetSymbolAddress((void**)&vL,   g_vL);
    cudaGetSymbolAddress((void**)&sc,   g_sc);
    cudaGetSymbolAddress((void**)&scH,  g_scH);
    cudaGetSymbolAddress((void**)&scL,  g_scL);
    cudaGetSymbolAddress((void**)&hidH, g_hidH);
    cudaGetSymbolAddress((void**)&hidL, g_hidL);
    cudaGetSymbolAddress((void**)&WqH,  g_WqH);
    cudaGetSymbolAddress((void**)&WqL,  g_WqL);
    cudaGetSymbolAddress((void**)&WkH,  g_WkH);
    cudaGetSymbolAddress((void**)&WkL,  g_WkL);
    cudaGetSymbolAddress((void**)&WvH,  g_WvH);
    cudaGetSymbolAddress((void**)&WvL,  g_WvL);
    cudaGetSymbolAddress((void**)&W1H,  g_W1H);
    cudaGetSymbolAddress((void**)&W1L,  g_W1L);
    cudaGetSymbolAddress((void**)&W2H,  g_W2H);
    cudaGetSymbolAddress((void**)&W2L,  g_W2L);

    cudaFuncSetAttribute(tc_gemm<false, false, false, true>,
                         cudaFuncAttributeMaxDynamicSharedMemorySize, TC_SMEM);
    cudaFuncSetAttribute(tc_gemm<false, true, false, true>,
                         cudaFuncAttributeMaxDynamicSharedMemorySize, TC_SMEM);
    cudaFuncSetAttribute(tc_gemm<true, false, true, false>,
                         cudaFuncAttributeMaxDynamicSharedMemorySize, TC_SMEM);
    cudaFuncSetAttribute(tc_gemm<false, false, true, false>,
                         cudaFuncAttributeMaxDynamicSharedMemorySize, TC_SMEM);

    const long long TD = (long long)SEQ * D_MODEL;
    const long long SS = (long long)SEQ * SEQ;
    const float inv_sqrt_d = 0.03125f;

    // ---- pre-split all weights (per replay; ~130 us total)
    {
        int nq = NLAYERS * D_MODEL * D_MODEL / 4;
        int n1 = NLAYERS * D_MODEL * DFF / 4;
        split_kernel<<<nq / 256, 256>>>(Wq, WqH, WqL, nq);
        split_kernel<<<nq / 256, 256>>>(Wk, WkH, WkL, nq);
        split_kernel<<<nq / 256, 256>>>(Wv, WvH, WvL, nq);
        split_kernel<<<n1 / 256, 256>>>(W1, W1H, W1L, n1);
        split_kernel<<<n1 / 256, 256>>>(W2, W2H, W2L, n1);
    }

    embed_kernel<<<NTOK, 256>>>(tokens, emb, x);

    for (int l = 0; l < NLAYERS; l++) {
        size_t oQ = (size_t)l * D_MODEL * D_MODEL;
        size_t o1 = (size_t)l * D_MODEL * DFF;

        ln_kernel<<<NTOK, 256>>>(x, g1 + l * D_MODEL, beta1 + l * D_MODEL, lnH, lnL);

        dim3 gQKV(D_MODEL / 128, NTOK / 128, 1);
        tc_gemm<false, false, false, true><<<gQKV, 256, TC_SMEM>>>(
            lnH, lnL, WqH + oQ, WqL + oQ, nullptr, qH, qL,
            bq + l * D_MODEL, nullptr, NTOK, D_MODEL, D_MODEL, 1.f, 0, 0, 0);
        tc_gemm<false, false, false, true><<<gQKV, 256, TC_SMEM>>>(
            lnH, lnL, WkH + oQ, WkL + oQ, nullptr, kH, kL,
            bk + l * D_MODEL, nullptr, NTOK, D_MODEL, D_MODEL, 1.f, 0, 0, 0);
        tc_gemm<false, false, false, true><<<gQKV, 256, TC_SMEM>>>(
            lnH, lnL, WvH + oQ, WvL + oQ, nullptr, vH, vL,
            bv + l * D_MODEL, nullptr, NTOK, D_MODEL, D_MODEL, 1.f, 0, 0, 0);

        dim3 gSC(SEQ / 128, SEQ / 128, BATCH);
        tc_gemm<true, false, true, false><<<gSC, 256, TC_SMEM>>>(
            qH, qL, kH, kL, sc, nullptr, nullptr,
            nullptr, nullptr, SEQ, SEQ, D_MODEL, inv_sqrt_d, TD, TD, SS);

        softmax_kernel<<<BATCH * SEQ, 256>>>(sc, scH, scL);

        dim3 gAV(D_MODEL / 128, SEQ / 128, BATCH);
        tc_gemm<false, false, true, false><<<gAV, 256, TC_SMEM>>>(
            scH, scL, vH, vL, x, nullptr, nullptr,
            nullptr, x, SEQ, D_MODEL, SEQ, 1.f, SS, TD, TD);

        ln_kernel<<<NTOK, 256>>>(x, g2 + l * D_MODEL, beta2 + l * D_MODEL, lnH, lnL);

        dim3 gM1(DFF / 128, NTOK / 128, 1);
        tc_gemm<false, true, false, true><<<gM1, 256, TC_SMEM>>>(
            lnH, lnL, W1H + o1, W1L + o1, nullptr, hidH, hidL,
            bm1 + l * DFF, nullptr, NTOK, DFF, D_MODEL, 1.f, 0, 0, 0);

        dim3 gM2(D_MODEL / 128, NTOK / 128, 1);
        tc_gemm<false, false, true, false><<<gM2, 256, TC_SMEM>>>(
            hidH, hidL, W2H + o1, W2L + o1, x, nullptr, nullptr,
            bm2 + l * D_MODEL, x, NTOK, D_MODEL, DFF, 1.f, 0, 0, 0);
    }
}

// round 6
// speedup vs baseline: 2.9832x; 1.0425x over previous
#include <cuda_runtime.h>
#include <cuda_bf16.h>
#include <math.h>
#include <stdint.h>

// ---------------------------------------------------------------------------
// Problem constants
// ---------------------------------------------------------------------------
#define D_MODEL 1024
#define DFF     4096
#define NLAYERS 8
#define BATCH   4
#define SEQ     2048
#define NTOK    (BATCH * SEQ)      // 8192
#define EPS     1e-5f

typedef __nv_bfloat16 bf16;

// ---------------------------------------------------------------------------
// Device scratch (allocation-free rule: __device__ globals)
// ---------------------------------------------------------------------------
__device__ bf16  g_lnH [NTOK * D_MODEL];
__device__ bf16  g_lnL [NTOK * D_MODEL];
__device__ bf16  g_qkvH[3 * NTOK * D_MODEL];
__device__ bf16  g_qkvL[3 * NTOK * D_MODEL];
__device__ float g_sc  [BATCH * SEQ * SEQ];
__device__ bf16  g_scH [BATCH * SEQ * SEQ];
__device__ bf16  g_scL [BATCH * SEQ * SEQ];
__device__ bf16  g_hidH[NTOK * DFF];
__device__ bf16  g_hidL[NTOK * DFF];
// pre-split weights; QKV interleaved per layer: [L][3][D*D]
__device__ bf16  g_WqkvH[NLAYERS * 3 * D_MODEL * D_MODEL];
__device__ bf16  g_WqkvL[NLAYERS * 3 * D_MODEL * D_MODEL];
__device__ bf16  g_W1H[NLAYERS * D_MODEL * DFF];
__device__ bf16  g_W1L[NLAYERS * D_MODEL * DFF];
__device__ bf16  g_W2H[NLAYERS * DFF * D_MODEL];
__device__ bf16  g_W2L[NLAYERS * DFF * D_MODEL];
// concatenated QKV bias: [L][3][D]
__device__ float g_bqkv[NLAYERS * 3 * D_MODEL];

// ---------------------------------------------------------------------------
// PTX helpers
// ---------------------------------------------------------------------------
__device__ __forceinline__ uint32_t smem_u32(const void* p) {
    uint32_t a;
    asm("{ .reg .u64 t; cvta.to.shared.u64 t, %1; cvt.u32.u64 %0, t; }"
        : "=r"(a) : "l"(p));
    return a;
}

__device__ __forceinline__ void ldsm_x4(uint32_t* r, uint32_t addr) {
    asm volatile("ldmatrix.sync.aligned.m8n8.x4.shared.b16 {%0,%1,%2,%3}, [%4];"
                 : "=r"(r[0]), "=r"(r[1]), "=r"(r[2]), "=r"(r[3]) : "r"(addr));
}

__device__ __forceinline__ void ldsm_x4_t(uint32_t* r, uint32_t addr) {
    asm volatile("ldmatrix.sync.aligned.m8n8.x4.trans.shared.b16 {%0,%1,%2,%3}, [%4];"
                 : "=r"(r[0]), "=r"(r[1]), "=r"(r[2]), "=r"(r[3]) : "r"(addr));
}

__device__ __forceinline__ void mma_bf16(float* c, const uint32_t* a, const uint32_t* b) {
    asm volatile(
        "mma.sync.aligned.m16n8k16.row.col.f32.bf16.bf16.f32 "
        "{%0,%1,%2,%3}, {%4,%5,%6,%7}, {%8,%9}, {%0,%1,%2,%3};"
        : "+f"(c[0]), "+f"(c[1]), "+f"(c[2]), "+f"(c[3])
        : "r"(a[0]), "r"(a[1]), "r"(a[2]), "r"(a[3]), "r"(b[0]), "r"(b[1]));
}

__device__ __forceinline__ void cp_async16(uint32_t saddr, const void* gptr) {
    asm volatile("cp.async.cg.shared.global [%0], [%1], 16;"
                 :: "r"(saddr), "l"(gptr) : "memory");
}
__device__ __forceinline__ void cp_commit() {
    asm volatile("cp.async.commit_group;" ::: "memory");
}
__device__ __forceinline__ void cp_wait_all() {
    asm volatile("cp.async.wait_group 0;" ::: "memory");
}

__device__ __forceinline__ uint32_t pack2(bf16 a, bf16 b) {
    return ((uint32_t)__bfloat16_as_ushort(b) << 16) | __bfloat16_as_ushort(a);
}

__device__ __forceinline__ void split4(const float4 v, uint32_t* hi, uint32_t* lo) {
    bf16 h0 = __float2bfloat16(v.x);
    bf16 h1 = __float2bfloat16(v.y);
    bf16 h2 = __float2bfloat16(v.z);
    bf16 h3 = __float2bfloat16(v.w);
    hi[0] = pack2(h0, h1);
    hi[1] = pack2(h2, h3);
    lo[0] = pack2(__float2bfloat16(v.x - __bfloat162float(h0)),
                  __float2bfloat16(v.y - __bfloat162float(h1)));
    lo[1] = pack2(__float2bfloat16(v.z - __bfloat162float(h2)),
                  __float2bfloat16(v.w - __bfloat162float(h3)));
}

// ---------------------------------------------------------------------------
// Weight pre-split kernels
// ---------------------------------------------------------------------------
__global__ __launch_bounds__(256)
void split_kernel(const float* __restrict__ in,
                  bf16* __restrict__ oh, bf16* __restrict__ ol, int n4)
{
    int i = blockIdx.x * 256 + threadIdx.x;
    if (i >= n4) return;
    float4 v = ((const float4*)in)[i];
    uint32_t hi[2], lo[2];
    split4(v, hi, lo);
    ((uint2*)oh)[i] = make_uint2(hi[0], hi[1]);
    ((uint2*)ol)[i] = make_uint2(lo[0], lo[1]);
}

// interleave per-layer: src [L][S], dst [L][3][S] slot j
__global__ __launch_bounds__(256)
void split_qkv_kernel(const float* __restrict__ in,
                      bf16* __restrict__ oh, bf16* __restrict__ ol,
                      int n4, int S4, int j)
{
    int i = blockIdx.x * 256 + threadIdx.x;
    if (i >= n4) return;
    int l = i / S4;
    int rem = i - l * S4;
    int d = (l * 3 + j) * S4 + rem;
    float4 v = ((const float4*)in)[i];
    uint32_t hi[2], lo[2];
    split4(v, hi, lo);
    ((uint2*)oh)[d] = make_uint2(hi[0], hi[1]);
    ((uint2*)ol)[d] = make_uint2(lo[0], lo[1]);
}

__global__ __launch_bounds__(256)
void concat_bias_kernel(const float* __restrict__ bq,
                        const float* __restrict__ bk,
                        const float* __restrict__ bv,
                        float* __restrict__ out)
{
    int i = blockIdx.x * 256 + threadIdx.x;   // over NLAYERS * D_MODEL
    int l = i / D_MODEL;
    int d = i - l * D_MODEL;
    out[(l * 3 + 0) * D_MODEL + d] = bq[i];
    out[(l * 3 + 1) * D_MODEL + d] = bk[i];
    out[(l * 3 + 2) * D_MODEL + d] = bv[i];
}

// ---------------------------------------------------------------------------
// Embedding + sinusoidal PE
// ---------------------------------------------------------------------------
__global__ __launch_bounds__(256)
void embed_kernel(const int* __restrict__ tokens,
                  const float* __restrict__ emb,
                  float* __restrict__ out)
{
    int row = blockIdx.x;
    int s   = row & (SEQ - 1);
    int tok = tokens[row];
    int d   = threadIdx.x * 4;

    float4 e = *(const float4*)&emb[(size_t)tok * D_MODEL + d];
    float o[4] = { e.x, e.y, e.z, e.w };
#pragma unroll
    for (int i = 0; i < 4; i++) {
        int dd = d + i;
        float freq = expf((float)(dd & ~1) * (-9.210340371976184f / (float)D_MODEL));
        float a = (float)s * freq;
        o[i] += (dd & 1) ? cosf(a) : sinf(a);
    }
    *(float4*)&out[(size_t)row * D_MODEL + d] = make_float4(o[0], o[1], o[2], o[3]);
}

// ---------------------------------------------------------------------------
// LayerNorm: fp32 in -> hi/lo bf16 out
// ---------------------------------------------------------------------------
__global__ __launch_bounds__(256)
void ln_kernel(const float* __restrict__ x,
               const float* __restrict__ g,
               const float* __restrict__ b,
               bf16* __restrict__ oh, bf16* __restrict__ ol)
{
    __shared__ float red[8];
    __shared__ float s_stat;

    int row = blockIdx.x;
    int tid = threadIdx.x;
    const float4* xr = (const float4*)(x + (size_t)row * D_MODEL);
    float4 v = xr[tid];

    float s = v.x + v.y + v.z + v.w;
#pragma unroll
    for (int o = 16; o > 0; o >>= 1) s += __shfl_xor_sync(0xffffffffu, s, o);
    if ((tid & 31) == 0) red[tid >> 5] = s;
    __syncthreads();
    if (tid == 0) {
        float t = 0.f;
#pragma unroll
        for (int i = 0; i < 8; i++) t += red[i];
        s_stat = t * (1.0f / D_MODEL);
    }
    __syncthreads();
    float mean = s_stat;

    float4 d;
    d.x = v.x - mean; d.y = v.y - mean; d.z = v.z - mean; d.w = v.w - mean;

    float s2 = d.x * d.x + d.y * d.y + d.z * d.z + d.w * d.w;
#pragma unroll
    for (int o = 16; o > 0; o >>= 1) s2 += __shfl_xor_sync(0xffffffffu, s2, o);
    if ((tid & 31) == 0) red[tid >> 5] = s2;
    __syncthreads();
    if (tid == 0) {
        float t = 0.f;
#pragma unroll
        for (int i = 0; i < 8; i++) t += red[i];
        s_stat = rsqrtf(t * (1.0f / D_MODEL) + EPS);
    }
    __syncthreads();
    float rstd = s_stat;

    float4 gg = *(const float4*)&g[tid * 4];
    float4 bb = *(const float4*)&b[tid * 4];
    float4 o4;
    o4.x = d.x * rstd * gg.x + bb.x;
    o4.y = d.y * rstd * gg.y + bb.y;
    o4.z = d.z * rstd * gg.z + bb.z;
    o4.w = d.w * rstd * gg.w + bb.w;

    uint32_t hi[2], lo[2];
    split4(o4, hi, lo);
    ((uint2*)(oh + (size_t)row * D_MODEL))[tid] = make_uint2(hi[0], hi[1]);
    ((uint2*)(ol + (size_t)row * D_MODEL))[tid] = make_uint2(lo[0], lo[1]);
}

// ---------------------------------------------------------------------------
// Softmax: fp32 in -> hi/lo bf16 out
// ---------------------------------------------------------------------------
__global__ __launch_bounds__(256)
void softmax_kernel(const float* __restrict__ sc,
                    bf16* __restrict__ oh, bf16* __restrict__ ol)
{
    __shared__ float red[8];
    __shared__ float s_val;

    size_t row = blockIdx.x;
    const float4* p = (const float4*)(sc + row * SEQ);
    int tid = threadIdx.x;

    float4 v0 = p[tid];
    float4 v1 = p[tid + 256];

    float m = fmaxf(fmaxf(fmaxf(v0.x, v0.y), fmaxf(v0.z, v0.w)),
                    fmaxf(fmaxf(v1.x, v1.y), fmaxf(v1.z, v1.w)));
#pragma unroll
    for (int o = 16; o > 0; o >>= 1) m = fmaxf(m, __shfl_xor_sync(0xffffffffu, m, o));
    if ((tid & 31) == 0) red[tid >> 5] = m;
    __syncthreads();
    if (tid == 0) {
        float t = red[0];
#pragma unroll
        for (int i = 1; i < 8; i++) t = fmaxf(t, red[i]);
        s_val = t;
    }
    __syncthreads();
    m = s_val;

    v0.x = expf(v0.x - m); v0.y = expf(v0.y - m);
    v0.z = expf(v0.z - m); v0.w = expf(v0.w - m);
    v1.x = expf(v1.x - m); v1.y = expf(v1.y - m);
    v1.z = expf(v1.z - m); v1.w = expf(v1.w - m);

    float s = v0.x + v0.y + v0.z + v0.w + v1.x + v1.y + v1.z + v1.w;
#pragma unroll
    for (int o = 16; o > 0; o >>= 1) s += __shfl_xor_sync(0xffffffffu, s, o);
    if ((tid & 31) == 0) red[tid >> 5] = s;
    __syncthreads();
    if (tid == 0) {
        float t = 0.f;
#pragma unroll
        for (int i = 0; i < 8; i++) t += red[i];
        s_val = t;
    }
    __syncthreads();
    float inv = 1.0f / s_val;

    v0.x *= inv; v0.y *= inv; v0.z *= inv; v0.w *= inv;
    v1.x *= inv; v1.y *= inv; v1.z *= inv; v1.w *= inv;

    uint32_t hi[2], lo[2];
    split4(v0, hi, lo);
    ((uint2*)(oh + row * SEQ))[tid] = make_uint2(hi[0], hi[1]);
    ((uint2*)(ol + row * SEQ))[tid] = make_uint2(lo[0], lo[1]);
    split4(v1, hi, lo);
    ((uint2*)(oh + row * SEQ))[tid + 256] = make_uint2(hi[0], hi[1]);
    ((uint2*)(ol + row * SEQ))[tid + 256] = make_uint2(lo[0], lo[1]);
}

// ---------------------------------------------------------------------------
// Pure-bf16 split-3 warp-MMA GEMM, 2 CTAs/SM, B-fragment reuse.
// ---------------------------------------------------------------------------
#define A_STRIDE_B   80
#define A_TILE_B     10240
#define BNN_STRIDE_B 272
#define BNN_TILE_B   8704
#define STAGE_B      40960
#define TC_SMEM      (2 * STAGE_B)

template<bool TRANSB>
__device__ __forceinline__ void load_chunk(
    uint32_t stg, const bf16* Ah, const bf16* Al,
    const bf16* Bh, const bf16* Bl,
    int rowBase, int colBase, int kb, int N, int K, int tid)
{
    const uint32_t aH = stg;
    const uint32_t aL = stg + A_TILE_B;
    const uint32_t bH = stg + 2 * A_TILE_B;
    const uint32_t bL = bH + (TRANSB ? A_TILE_B : BNN_TILE_B);

#pragma unroll
    for (int i = 0; i < 2; i++) {
        int id = tid + (i << 8);
        int r = id >> 2;
        int c8 = (id & 3) << 3;
        uint32_t so = (uint32_t)r * A_STRIDE_B + (uint32_t)(c8 << 1);
        size_t go = (size_t)(rowBase + r) * K + kb + c8;
        cp_async16(aH + so, Ah + go);
        cp_async16(aL + so, Al + go);
    }
    if (TRANSB) {
#pragma unroll
        for (int i = 0; i < 2; i++) {
            int id = tid + (i << 8);
            int r = id >> 2;
            int c8 = (id & 3) << 3;
            uint32_t so = (uint32_t)r * A_STRIDE_B + (uint32_t)(c8 << 1);
            size_t go = (size_t)(colBase + r) * K + kb + c8;
            cp_async16(bH + so, Bh + go);
            cp_async16(bL + so, Bl + go);
        }
    } else {
#pragma unroll
        for (int i = 0; i < 2; i++) {
            int id = tid + (i << 8);
            int r = id >> 4;
            int c8 = (id & 15) << 3;
            uint32_t so = (uint32_t)r * BNN_STRIDE_B + (uint32_t)(c8 << 1);
            size_t go = (size_t)(kb + r) * N + colBase + c8;
            cp_async16(bH + so, Bh + go);
            cp_async16(bL + so, Bl + go);
        }
    }
    cp_commit();
}

template<bool TRANSB, bool RELU, bool OF32, bool OB16>
__global__ __launch_bounds__(256, 2)
void tc_gemm(const bf16* __restrict__ Ah, const bf16* __restrict__ Al,
             const bf16* __restrict__ Bh, const bf16* __restrict__ Bl,
             float* __restrict__ Cf,
             bf16* __restrict__ Ch, bf16* __restrict__ Cl,
             const float* __restrict__ bias,
             const float* __restrict__ residual,
             int M, int N, int K, float alpha,
             long long strA, long long strB, long long strC, long long strBias)
{
    extern __shared__ char smem[];
    const uint32_t sb = smem_u32(smem);
    const int tid  = threadIdx.x;
    const int wid  = tid >> 5;
    const int lane = tid & 31;
    const int wm   = wid >> 1;
    const int wn   = wid & 1;

    long long bz = blockIdx.z;
    Ah += bz * strA; Al += bz * strA;
    Bh += bz * strB; Bl += bz * strB;
    if (OF32) Cf += bz * strC;
    if (OB16) { Ch += bz * strC; Cl += bz * strC; }
    if (bias) bias += bz * strBias;
    const float* Rres = (OF32 && residual) ? residual + bz * strC : nullptr;

    const int rowBase = blockIdx.y * 128;
    const int colBase = blockIdx.x * 128;

    float acc[2][8][4];
#pragma unroll
    for (int i = 0; i < 2; i++)
#pragma unroll
        for (int j = 0; j < 8; j++)
#pragma unroll
            for (int t = 0; t < 4; t++) acc[i][j][t] = 0.f;

    const int nch = K >> 5;

    load_chunk<TRANSB>(sb, Ah, Al, Bh, Bl, rowBase, colBase, 0, N, K, tid);

    for (int c = 0; c < nch; c++) {
        const uint32_t stg = sb + (uint32_t)(c & 1) * STAGE_B;
        const uint32_t aH = stg;
        const uint32_t aL = stg + A_TILE_B;
        const uint32_t bH = stg + 2 * A_TILE_B;
        const uint32_t bL = bH + (TRANSB ? A_TILE_B : BNN_TILE_B);

        cp_wait_all();
        __syncthreads();

        if (c + 1 < nch)
            load_chunk<TRANSB>(sb + (uint32_t)((c + 1) & 1) * STAGE_B,
                               Ah, Al, Bh, Bl, rowBase, colBase,
                               (c + 1) * 32, N, K, tid);

        // compute: per (ks, p): ldsm bh -> HH x4 -> ldsm bl -> LH x4 -> HL x4
#pragma unroll
        for (int ks = 0; ks < 2; ks++) {
            uint32_t ah[2][4], al[2][4];
#pragma unroll
            for (int mt = 0; mt < 2; mt++) {
                uint32_t off = (uint32_t)(wm * 32 + mt * 16 + (lane & 15)) * A_STRIDE_B
                             + (uint32_t)(ks * 16 + (lane >> 4) * 8) * 2;
                ldsm_x4(ah[mt], aH + off);
                ldsm_x4(al[mt], aL + off);
            }
#pragma unroll
            for (int p = 0; p < 4; p++) {
                uint32_t off;
                if (TRANSB) {
                    off = (uint32_t)(wn * 64 + p * 16 + (lane & 7) + ((lane >> 4) & 1) * 8) * A_STRIDE_B
                        + (uint32_t)(ks * 16 + ((lane >> 3) & 1) * 8) * 2;
                } else {
                    off = (uint32_t)(ks * 16 + (lane & 7) + ((lane >> 3) & 1) * 8) * BNN_STRIDE_B
                        + (uint32_t)(wn * 64 + p * 16 + (lane >> 4) * 8) * 2;
                }
                uint32_t bh[4], bl[4];
                if (TRANSB) ldsm_x4(bh, bH + off); else ldsm_x4_t(bh, bH + off);
                // HH
#pragma unroll
                for (int mt = 0; mt < 2; mt++)
#pragma unroll
                    for (int g = 0; g < 2; g++)
                        mma_bf16(acc[mt][p * 2 + g], ah[mt], bh + 2 * g);
                if (TRANSB) ldsm_x4(bl, bL + off); else ldsm_x4_t(bl, bL + off);
                // LH (reuses bh, hides bl latency)
#pragma unroll
                for (int mt = 0; mt < 2; mt++)
#pragma unroll
                    for (int g = 0; g < 2; g++)
                        mma_bf16(acc[mt][p * 2 + g], al[mt], bh + 2 * g);
                // HL
#pragma unroll
                for (int mt = 0; mt < 2; mt++)
#pragma unroll
                    for (int g = 0; g < 2; g++)
                        mma_bf16(acc[mt][p * 2 + g], ah[mt], bl + 2 * g);
            }
        }
        __syncthreads();
    }

    // ---- epilogue
#pragma unroll
    for (int mt = 0; mt < 2; mt++) {
        int r0 = rowBase + wm * 32 + mt * 16 + (lane >> 2);
#pragma unroll
        for (int ng = 0; ng < 8; ng++) {
            int col = colBase + wn * 64 + ng * 8 + (lane & 3) * 2;
            float2 v0, v1;
            v0.x = alpha * acc[mt][ng][0];
            v0.y = alpha * acc[mt][ng][1];
            v1.x = alpha * acc[mt][ng][2];
            v1.y = alpha * acc[mt][ng][3];
            if (bias) {
                float2 bb = *(const float2*)&bias[col];
                v0.x += bb.x; v0.y += bb.y;
                v1.x += bb.x; v1.y += bb.y;
            }
            if (RELU) {
                v0.x = fmaxf(v0.x, 0.f); v0.y = fmaxf(v0.y, 0.f);
                v1.x = fmaxf(v1.x, 0.f); v1.y = fmaxf(v1.y, 0.f);
            }
            if (OF32) {
                float2 w0 = v0, w1 = v1;
                if (Rres) {
                    float2 q0 = *(const float2*)&Rres[(size_t)r0 * N + col];
                    float2 q1 = *(const float2*)&Rres[(size_t)(r0 + 8) * N + col];
                    w0.x += q0.x; w0.y += q0.y;
                    w1.x += q1.x; w1.y += q1.y;
                }
                *(float2*)&Cf[(size_t)r0 * N + col]       = w0;
                *(float2*)&Cf[(size_t)(r0 + 8) * N + col] = w1;
            }
            if (OB16) {
                bf16 h0 = __float2bfloat16(v0.x);
                bf16 h1 = __float2bfloat16(v0.y);
                bf16 h2 = __float2bfloat16(v1.x);
                bf16 h3 = __float2bfloat16(v1.y);
                *(uint32_t*)&Ch[(size_t)r0 * N + col] = pack2(h0, h1);
                *(uint32_t*)&Ch[(size_t)(r0 + 8) * N + col] = pack2(h2, h3);
                *(uint32_t*)&Cl[(size_t)r0 * N + col] =
                    pack2(__float2bfloat16(v0.x - __bfloat162float(h0)),
                          __float2bfloat16(v0.y - __bfloat162float(h1)));
                *(uint32_t*)&Cl[(size_t)(r0 + 8) * N + col] =
                    pack2(__float2bfloat16(v1.x - __bfloat162float(h2)),
                          __float2bfloat16(v1.y - __bfloat162float(h3)));
            }
        }
    }
}

// ---------------------------------------------------------------------------
// Host launcher
// ---------------------------------------------------------------------------
extern "C" void kernel_launch(void* const* d_in, const int* in_sizes, int n_in,
                              void* d_out, int out_size)
{
    const int*   tokens = (const int*)  d_in[0];
    const float* emb    = (const float*)d_in[1];
    const float* Wq     = (const float*)d_in[2];
    const float* bq     = (const float*)d_in[3];
    const float* Wk     = (const float*)d_in[4];
    const float* bk     = (const float*)d_in[5];
    const float* Wv     = (const float*)d_in[6];
    const float* bv     = (const float*)d_in[7];
    const float* g1     = (const float*)d_in[8];
    const float* beta1  = (const float*)d_in[9];
    const float* g2     = (const float*)d_in[10];
    const float* beta2  = (const float*)d_in[11];
    const float* W1     = (const float*)d_in[12];
    const float* bm1    = (const float*)d_in[13];
    const float* W2     = (const float*)d_in[14];
    const float* bm2    = (const float*)d_in[15];

    float* x = (float*)d_out;

    bf16 *lnH, *lnL, *qkvH, *qkvL, *scH, *scL, *hidH, *hidL;
    bf16 *WqkvH, *WqkvL, *W1H, *W1L, *W2H, *W2L;
    float *sc, *bqkv;
    cudaGetSymbolAddress((void**)&lnH,   g_lnH);
    cudaGetSymbolAddress((void**)&lnL,   g_lnL);
    cudaGetSymbolAddress((void**)&qkvH,  g_qkvH);
    cudaGetSymbolAddress((void**)&qkvL,  g_qkvL);
    cudaGetSymbolAddress((void**)&sc,    g_sc);
    cudaGetSymbolAddress((void**)&scH,   g_scH);
    cudaGetSymbolAddress((void**)&scL,   g_scL);
    cudaGetSymbolAddress((void**)&hidH,  g_hidH);
    cudaGetSymbolAddress((void**)&hidL,  g_hidL);
    cudaGetSymbolAddress((void**)&WqkvH, g_WqkvH);
    cudaGetSymbolAddress((void**)&WqkvL, g_WqkvL);
    cudaGetSymbolAddress((void**)&W1H,   g_W1H);
    cudaGetSymbolAddress((void**)&W1L,   g_W1L);
    cudaGetSymbolAddress((void**)&W2H,   g_W2H);
    cudaGetSymbolAddress((void**)&W2L,   g_W2L);
    cudaGetSymbolAddress((void**)&bqkv,  g_bqkv);

    cudaFuncSetAttribute(tc_gemm<false, false, false, true>,
                         cudaFuncAttributeMaxDynamicSharedMemorySize, TC_SMEM);
    cudaFuncSetAttribute(tc_gemm<false, true, false, true>,
                         cudaFuncAttributeMaxDynamicSharedMemorySize, TC_SMEM);
    cudaFuncSetAttribute(tc_gemm<true, false, true, false>,
                         cudaFuncAttributeMaxDynamicSharedMemorySize, TC_SMEM);
    cudaFuncSetAttribute(tc_gemm<false, false, true, false>,
                         cudaFuncAttributeMaxDynamicSharedMemorySize, TC_SMEM);

    const long long TD = (long long)SEQ * D_MODEL;
    const long long SS = (long long)SEQ * SEQ;
    const float inv_sqrt_d = 0.03125f;

    bf16* qH = qkvH;
    bf16* qL = qkvL;
    bf16* kH = qkvH + (size_t)NTOK * D_MODEL;
    bf16* kL = qkvL + (size_t)NTOK * D_MODEL;
    bf16* vH = qkvH + 2 * (size_t)NTOK * D_MODEL;
    bf16* vL = qkvL + 2 * (size_t)NTOK * D_MODEL;

    // ---- pre-split weights & biases
    {
        int S4 = D_MODEL * D_MODEL / 4;
        int nq = NLAYERS * S4;
        int n1 = NLAYERS * D_MODEL * DFF / 4;
        split_qkv_kernel<<<nq / 256, 256>>>(Wq, WqkvH, WqkvL, nq, S4, 0);
        split_qkv_kernel<<<nq / 256, 256>>>(Wk, WqkvH, WqkvL, nq, S4, 1);
        split_qkv_kernel<<<nq / 256, 256>>>(Wv, WqkvH, WqkvL, nq, S4, 2);
        split_kernel<<<n1 / 256, 256>>>(W1, W1H, W1L, n1);
        split_kernel<<<n1 / 256, 256>>>(W2, W2H, W2L, n1);
        concat_bias_kernel<<<NLAYERS * D_MODEL / 256, 256>>>(bq, bk, bv, bqkv);
    }

    embed_kernel<<<NTOK, 256>>>(tokens, emb, x);

    for (int l = 0; l < NLAYERS; l++) {
        size_t oQ = (size_t)l * 3 * D_MODEL * D_MODEL;
        size_t o1 = (size_t)l * D_MODEL * DFF;

        ln_kernel<<<NTOK, 256>>>(x, g1 + l * D_MODEL, beta1 + l * D_MODEL, lnH, lnL);

        // fused QKV: grid.z selects {Q,K,V}
        dim3 gQKV(D_MODEL / 128, NTOK / 128, 3);
        tc_gemm<false, false, false, true><<<gQKV, 256, TC_SMEM>>>(
            lnH, lnL, WqkvH + oQ, WqkvL + oQ, nullptr, qkvH, qkvL,
            bqkv + (size_t)l * 3 * D_MODEL, nullptr,
            NTOK, D_MODEL, D_MODEL, 1.f,
            0, (long long)D_MODEL * D_MODEL, (long long)NTOK * D_MODEL, D_MODEL);

        dim3 gSC(SEQ / 128, SEQ / 128, BATCH);
        tc_gemm<true, false, true, false><<<gSC, 256, TC_SMEM>>>(
            qH, qL, kH, kL, sc, nullptr, nullptr,
            nullptr, nullptr, SEQ, SEQ, D_MODEL, inv_sqrt_d, TD, TD, SS, 0);

        softmax_kernel<<<BATCH * SEQ, 256>>>(sc, scH, scL);

        dim3 gAV(D_MODEL / 128, SEQ / 128, BATCH);
        tc_gemm<false, false, true, false><<<gAV, 256, TC_SMEM>>>(
            scH, scL, vH, vL, x, nullptr, nullptr,
            nullptr, x, SEQ, D_MODEL, SEQ, 1.f, SS, TD, TD, 0);

        ln_kernel<<<NTOK, 256>>>(x, g2 + l * D_MODEL, beta2 + l * D_MODEL, lnH, lnL);

        dim3 gM1(DFF / 128, NTOK / 128, 1);
        tc_gemm<false, true, false, true><<<gM1, 256, TC_SMEM>>>(
            lnH, lnL, W1H + o1, W1L + o1, nullptr, hidH, hidL,
            bm1 + l * DFF, nullptr, NTOK, DFF, D_MODEL, 1.f, 0, 0, 0, 0);

        dim3 gM2(D_MODEL / 128, NTOK / 128, 1);
        tc_gemm<false, false, true, false><<<gM2, 256, TC_SMEM>>>(
            hidH, hidL, W2H + o1, W2L + o1, x, nullptr, nullptr,
            bm2 + l * D_MODEL, x, NTOK, D_MODEL, DFF, 1.f, 0, 0, 0, 0);
    }
}

// round 7
// speedup vs baseline: 3.5429x; 1.1876x over previous
#include <cuda_runtime.h>
#include <cuda_bf16.h>
#include <cuda_fp16.h>
#include <math.h>
#include <stdint.h>

// ---------------------------------------------------------------------------
// Problem constants
// ---------------------------------------------------------------------------
#define D_MODEL 1024
#define DFF     4096
#define NLAYERS 8
#define BATCH   4
#define SEQ     2048
#define NTOK    (BATCH * SEQ)      // 8192
#define EPS     1e-5f

typedef __nv_bfloat16 bf16;

// ---------------------------------------------------------------------------
// Device scratch (allocation-free rule: __device__ globals)
// ---------------------------------------------------------------------------
__device__ bf16   g_lnH [NTOK * D_MODEL];
__device__ bf16   g_lnL [NTOK * D_MODEL];
__device__ __half g_qkv16[3 * NTOK * D_MODEL];      // fp16 q,k,v
__device__ float  g_sc  [BATCH * SEQ * SEQ];
__device__ __half g_at16[BATCH * SEQ * SEQ];        // fp16 attention weights
__device__ bf16   g_hidH[NTOK * DFF];
__device__ bf16   g_hidL[NTOK * DFF];
// pre-split weights; QKV interleaved per layer: [L][3][D*D]
__device__ bf16   g_WqkvH[NLAYERS * 3 * D_MODEL * D_MODEL];
__device__ bf16   g_WqkvL[NLAYERS * 3 * D_MODEL * D_MODEL];
__device__ bf16   g_W1H[NLAYERS * D_MODEL * DFF];
__device__ bf16   g_W1L[NLAYERS * D_MODEL * DFF];
__device__ bf16   g_W2H[NLAYERS * DFF * D_MODEL];
__device__ bf16   g_W2L[NLAYERS * DFF * D_MODEL];
__device__ float  g_bqkv[NLAYERS * 3 * D_MODEL];

// ---------------------------------------------------------------------------
// PTX helpers
// ---------------------------------------------------------------------------
__device__ __forceinline__ uint32_t smem_u32(const void* p) {
    uint32_t a;
    asm("{ .reg .u64 t; cvta.to.shared.u64 t, %1; cvt.u32.u64 %0, t; }"
        : "=r"(a) : "l"(p));
    return a;
}

__device__ __forceinline__ void ldsm_x4(uint32_t* r, uint32_t addr) {
    asm volatile("ldmatrix.sync.aligned.m8n8.x4.shared.b16 {%0,%1,%2,%3}, [%4];"
                 : "=r"(r[0]), "=r"(r[1]), "=r"(r[2]), "=r"(r[3]) : "r"(addr));
}

__device__ __forceinline__ void ldsm_x4_t(uint32_t* r, uint32_t addr) {
    asm volatile("ldmatrix.sync.aligned.m8n8.x4.trans.shared.b16 {%0,%1,%2,%3}, [%4];"
                 : "=r"(r[0]), "=r"(r[1]), "=r"(r[2]), "=r"(r[3]) : "r"(addr));
}

__device__ __forceinline__ void mma_bf16(float* c, const uint32_t* a, const uint32_t* b) {
    asm volatile(
        "mma.sync.aligned.m16n8k16.row.col.f32.bf16.bf16.f32 "
        "{%0,%1,%2,%3}, {%4,%5,%6,%7}, {%8,%9}, {%0,%1,%2,%3};"
        : "+f"(c[0]), "+f"(c[1]), "+f"(c[2]), "+f"(c[3])
        : "r"(a[0]), "r"(a[1]), "r"(a[2]), "r"(a[3]), "r"(b[0]), "r"(b[1]));
}

__device__ __forceinline__ void mma_f16(float* c, const uint32_t* a, const uint32_t* b) {
    asm volatile(
        "mma.sync.aligned.m16n8k16.row.col.f32.f16.f16.f32 "
        "{%0,%1,%2,%3}, {%4,%5,%6,%7}, {%8,%9}, {%0,%1,%2,%3};"
        : "+f"(c[0]), "+f"(c[1]), "+f"(c[2]), "+f"(c[3])
        : "r"(a[0]), "r"(a[1]), "r"(a[2]), "r"(a[3]), "r"(b[0]), "r"(b[1]));
}

__device__ __forceinline__ void cp_async16(uint32_t saddr, const void* gptr) {
    asm volatile("cp.async.cg.shared.global [%0], [%1], 16;"
                 :: "r"(saddr), "l"(gptr) : "memory");
}
__device__ __forceinline__ void cp_commit() {
    asm volatile("cp.async.commit_group;" ::: "memory");
}
__device__ __forceinline__ void cp_wait_all() {
    asm volatile("cp.async.wait_group 0;" ::: "memory");
}

__device__ __forceinline__ uint32_t pack2(bf16 a, bf16 b) {
    return ((uint32_t)__bfloat16_as_ushort(b) << 16) | __bfloat16_as_ushort(a);
}

__device__ __forceinline__ uint32_t pack2h(float a, float b) {
    __half ha = __float2half_rn(a), hb = __float2half_rn(b);
    return ((uint32_t)__half_as_ushort(hb) << 16) | __half_as_ushort(ha);
}

__device__ __forceinline__ void split4(const float4 v, uint32_t* hi, uint32_t* lo) {
    bf16 h0 = __float2bfloat16(v.x);
    bf16 h1 = __float2bfloat16(v.y);
    bf16 h2 = __float2bfloat16(v.z);
    bf16 h3 = __float2bfloat16(v.w);
    hi[0] = pack2(h0, h1);
    hi[1] = pack2(h2, h3);
    lo[0] = pack2(__float2bfloat16(v.x - __bfloat162float(h0)),
                  __float2bfloat16(v.y - __bfloat162float(h1)));
    lo[1] = pack2(__float2bfloat16(v.z - __bfloat162float(h2)),
                  __float2bfloat16(v.w - __bfloat162float(h3)));
}

// ---------------------------------------------------------------------------
// Weight pre-split kernels
// ---------------------------------------------------------------------------
__global__ __launch_bounds__(256)
void split_kernel(const float* __restrict__ in,
                  bf16* __restrict__ oh, bf16* __restrict__ ol, int n4)
{
    int i = blockIdx.x * 256 + threadIdx.x;
    if (i >= n4) return;
    float4 v = ((const float4*)in)[i];
    uint32_t hi[2], lo[2];
    split4(v, hi, lo);
    ((uint2*)oh)[i] = make_uint2(hi[0], hi[1]);
    ((uint2*)ol)[i] = make_uint2(lo[0], lo[1]);
}

__global__ __launch_bounds__(256)
void split_qkv_kernel(const float* __restrict__ in,
                      bf16* __restrict__ oh, bf16* __restrict__ ol,
                      int n4, int S4, int j)
{
    int i = blockIdx.x * 256 + threadIdx.x;
    if (i >= n4) return;
    int l = i / S4;
    int rem = i - l * S4;
    int d = (l * 3 + j) * S4 + rem;
    float4 v = ((const float4*)in)[i];
    uint32_t hi[2], lo[2];
    split4(v, hi, lo);
    ((uint2*)oh)[d] = make_uint2(hi[0], hi[1]);
    ((uint2*)ol)[d] = make_uint2(lo[0], lo[1]);
}

__global__ __launch_bounds__(256)
void concat_bias_kernel(const float* __restrict__ bq,
                        const float* __restrict__ bk,
                        const float* __restrict__ bv,
                        float* __restrict__ out)
{
    int i = blockIdx.x * 256 + threadIdx.x;
    int l = i / D_MODEL;
    int d = i - l * D_MODEL;
    out[(l * 3 + 0) * D_MODEL + d] = bq[i];
    out[(l * 3 + 1) * D_MODEL + d] = bk[i];
    out[(l * 3 + 2) * D_MODEL + d] = bv[i];
}

// ---------------------------------------------------------------------------
// Embedding + sinusoidal PE
// ---------------------------------------------------------------------------
__global__ __launch_bounds__(256)
void embed_kernel(const int* __restrict__ tokens,
                  const float* __restrict__ emb,
                  float* __restrict__ out)
{
    int row = blockIdx.x;
    int s   = row & (SEQ - 1);
    int tok = tokens[row];
    int d   = threadIdx.x * 4;

    float4 e = *(const float4*)&emb[(size_t)tok * D_MODEL + d];
    float o[4] = { e.x, e.y, e.z, e.w };
#pragma unroll
    for (int i = 0; i < 4; i++) {
        int dd = d + i;
        float freq = expf((float)(dd & ~1) * (-9.210340371976184f / (float)D_MODEL));
        float a = (float)s * freq;
        o[i] += (dd & 1) ? cosf(a) : sinf(a);
    }
    *(float4*)&out[(size_t)row * D_MODEL + d] = make_float4(o[0], o[1], o[2], o[3]);
}

// ---------------------------------------------------------------------------
// LayerNorm: fp32 in -> hi/lo bf16 out
// ---------------------------------------------------------------------------
__global__ __launch_bounds__(256)
void ln_kernel(const float* __restrict__ x,
               const float* __restrict__ g,
               const float* __restrict__ b,
               bf16* __restrict__ oh, bf16* __restrict__ ol)
{
    __shared__ float red[8];
    __shared__ float s_stat;

    int row = blockIdx.x;
    int tid = threadIdx.x;
    const float4* xr = (const float4*)(x + (size_t)row * D_MODEL);
    float4 v = xr[tid];

    float s = v.x + v.y + v.z + v.w;
#pragma unroll
    for (int o = 16; o > 0; o >>= 1) s += __shfl_xor_sync(0xffffffffu, s, o);
    if ((tid & 31) == 0) red[tid >> 5] = s;
    __syncthreads();
    if (tid == 0) {
        float t = 0.f;
#pragma unroll
        for (int i = 0; i < 8; i++) t += red[i];
        s_stat = t * (1.0f / D_MODEL);
    }
    __syncthreads();
    float mean = s_stat;

    float4 d;
    d.x = v.x - mean; d.y = v.y - mean; d.z = v.z - mean; d.w = v.w - mean;

    float s2 = d.x * d.x + d.y * d.y + d.z * d.z + d.w * d.w;
#pragma unroll
    for (int o = 16; o > 0; o >>= 1) s2 += __shfl_xor_sync(0xffffffffu, s2, o);
    if ((tid & 31) == 0) red[tid >> 5] = s2;
    __syncthreads();
    if (tid == 0) {
        float t = 0.f;
#pragma unroll
        for (int i = 0; i < 8; i++) t += red[i];
        s_stat = rsqrtf(t * (1.0f / D_MODEL) + EPS);
    }
    __syncthreads();
    float rstd = s_stat;

    float4 gg = *(const float4*)&g[tid * 4];
    float4 bb = *(const float4*)&b[tid * 4];
    float4 o4;
    o4.x = d.x * rstd * gg.x + bb.x;
    o4.y = d.y * rstd * gg.y + bb.y;
    o4.z = d.z * rstd * gg.z + bb.z;
    o4.w = d.w * rstd * gg.w + bb.w;

    uint32_t hi[2], lo[2];
    split4(o4, hi, lo);
    ((uint2*)(oh + (size_t)row * D_MODEL))[tid] = make_uint2(hi[0], hi[1]);
    ((uint2*)(ol + (size_t)row * D_MODEL))[tid] = make_uint2(lo[0], lo[1]);
}

// ---------------------------------------------------------------------------
// Softmax: fp32 in -> fp16 out
// ---------------------------------------------------------------------------
__global__ __launch_bounds__(256)
void softmax_kernel(const float* __restrict__ sc, __half* __restrict__ oh)
{
    __shared__ float red[8];
    __shared__ float s_val;

    size_t row = blockIdx.x;
    const float4* p = (const float4*)(sc + row * SEQ);
    int tid = threadIdx.x;

    float4 v0 = p[tid];
    float4 v1 = p[tid + 256];

    float m = fmaxf(fmaxf(fmaxf(v0.x, v0.y), fmaxf(v0.z, v0.w)),
                    fmaxf(fmaxf(v1.x, v1.y), fmaxf(v1.z, v1.w)));
#pragma unroll
    for (int o = 16; o > 0; o >>= 1) m = fmaxf(m, __shfl_xor_sync(0xffffffffu, m, o));
    if ((tid & 31) == 0) red[tid >> 5] = m;
    __syncthreads();
    if (tid == 0) {
        float t = red[0];
#pragma unroll
        for (int i = 1; i < 8; i++) t = fmaxf(t, red[i]);
        s_val = t;
    }
    __syncthreads();
    m = s_val;

    v0.x = expf(v0.x - m); v0.y = expf(v0.y - m);
    v0.z = expf(v0.z - m); v0.w = expf(v0.w - m);
    v1.x = expf(v1.x - m); v1.y = expf(v1.y - m);
    v1.z = expf(v1.z - m); v1.w = expf(v1.w - m);

    float s = v0.x + v0.y + v0.z + v0.w + v1.x + v1.y + v1.z + v1.w;
#pragma unroll
    for (int o = 16; o > 0; o >>= 1) s += __shfl_xor_sync(0xffffffffu, s, o);
    if ((tid & 31) == 0) red[tid >> 5] = s;
    __syncthreads();
    if (tid == 0) {
        float t = 0.f;
#pragma unroll
        for (int i = 0; i < 8; i++) t += red[i];
        s_val = t;
    }
    __syncthreads();
    float inv = 1.0f / s_val;

    ((uint2*)(oh + row * SEQ))[tid] =
        make_uint2(pack2h(v0.x * inv, v0.y * inv), pack2h(v0.z * inv, v0.w * inv));
    ((uint2*)(oh + row * SEQ))[tid + 256] =
        make_uint2(pack2h(v1.x * inv, v1.y * inv), pack2h(v1.z * inv, v1.w * inv));
}

// ---------------------------------------------------------------------------
// Mixed-precision warp-MMA GEMM, 2 CTAs/SM.
// SPLIT=3: bf16 split-3 (Ah/Al, Bh/Bl).  SPLIT=1: fp16 single-pass (Ah, Bh).
// OMODE: 0 = fp32 out (+bias/relu/residual), 1 = bf16 hi/lo out, 2 = fp16 out.
// 16-bit storage is type-agnostic (bytes via cp.async/ldmatrix); the MMA
// instruction selects bf16 vs fp16 interpretation.
// ---------------------------------------------------------------------------
#define A_STRIDE_B   80
#define A_TILE_B     10240
#define BNN_STRIDE_B 272
#define BNN_TILE_B   8704
#define STAGE_B      40960
#define TC_SMEM      (2 * STAGE_B)

template<int SPLIT, bool TRANSB>
__device__ __forceinline__ void load_chunk(
    uint32_t stg, const bf16* Ah, const bf16* Al,
    const bf16* Bh, const bf16* Bl,
    int rowBase, int colBase, int kb, int N, int K, int tid)
{
    const uint32_t aH = stg;
    const uint32_t aL = stg + A_TILE_B;
    const uint32_t bH = (SPLIT == 3) ? stg + 2 * A_TILE_B : stg + A_TILE_B;
    const uint32_t bL = bH + (TRANSB ? A_TILE_B : BNN_TILE_B);

#pragma unroll
    for (int i = 0; i < 2; i++) {
        int id = tid + (i << 8);
        int r = id >> 2;
        int c8 = (id & 3) << 3;
        uint32_t so = (uint32_t)r * A_STRIDE_B + (uint32_t)(c8 << 1);
        size_t go = (size_t)(rowBase + r) * K + kb + c8;
        cp_async16(aH + so, Ah + go);
        if (SPLIT == 3) cp_async16(aL + so, Al + go);
    }
    if (TRANSB) {
#pragma unroll
        for (int i = 0; i < 2; i++) {
            int id = tid + (i << 8);
            int r = id >> 2;
            int c8 = (id & 3) << 3;
            uint32_t so = (uint32_t)r * A_STRIDE_B + (uint32_t)(c8 << 1);
            size_t go = (size_t)(colBase + r) * K + kb + c8;
            cp_async16(bH + so, Bh + go);
            if (SPLIT == 3) cp_async16(bL + so, Bl + go);
        }
    } else {
#pragma unroll
        for (int i = 0; i < 2; i++) {
            int id = tid + (i << 8);
            int r = id >> 4;
            int c8 = (id & 15) << 3;
            uint32_t so = (uint32_t)r * BNN_STRIDE_B + (uint32_t)(c8 << 1);
            size_t go = (size_t)(kb + r) * N + colBase + c8;
            cp_async16(bH + so, Bh + go);
            if (SPLIT == 3) cp_async16(bL + so, Bl + go);
        }
    }
    cp_commit();
}

template<int SPLIT, bool TRANSB, bool RELU, int OMODE>
__global__ __launch_bounds__(256, 2)
void tc_gemm(const bf16* __restrict__ Ah, const bf16* __restrict__ Al,
             const bf16* __restrict__ Bh, const bf16* __restrict__ Bl,
             float* __restrict__ Cf,
             bf16* __restrict__ C16h, bf16* __restrict__ C16l,
             const float* __restrict__ bias,
             const float* __restrict__ residual,
             int M, int N, int K, float alpha,
             long long strA, long long strB, long long strC, long long strBias)
{
    extern __shared__ char smem[];
    const uint32_t sb = smem_u32(smem);
    const int tid  = threadIdx.x;
    const int wid  = tid >> 5;
    const int lane = tid & 31;
    const int wm   = wid >> 1;
    const int wn   = wid & 1;

    long long bz = blockIdx.z;
    Ah += bz * strA;
    Bh += bz * strB;
    if (SPLIT == 3) { Al += bz * strA; Bl += bz * strB; }
    if (OMODE == 0) Cf += bz * strC;
    else { C16h += bz * strC; if (OMODE == 1) C16l += bz * strC; }
    if (bias) bias += bz * strBias;
    const float* Rres = (OMODE == 0 && residual) ? residual + bz * strC : nullptr;

    const int rowBase = blockIdx.y * 128;
    const int colBase = blockIdx.x * 128;

    float acc[2][8][4];
#pragma unroll
    for (int i = 0; i < 2; i++)
#pragma unroll
        for (int j = 0; j < 8; j++)
#pragma unroll
            for (int t = 0; t < 4; t++) acc[i][j][t] = 0.f;

    const int nch = K >> 5;

    load_chunk<SPLIT, TRANSB>(sb, Ah, Al, Bh, Bl, rowBase, colBase, 0, N, K, tid);

    for (int c = 0; c < nch; c++) {
        const uint32_t stg = sb + (uint32_t)(c & 1) * STAGE_B;
        const uint32_t aH = stg;
        const uint32_t aL = stg + A_TILE_B;
        const uint32_t bH = (SPLIT == 3) ? stg + 2 * A_TILE_B : stg + A_TILE_B;
        const uint32_t bL = bH + (TRANSB ? A_TILE_B : BNN_TILE_B);

        cp_wait_all();
        __syncthreads();

        if (c + 1 < nch)
            load_chunk<SPLIT, TRANSB>(sb + (uint32_t)((c + 1) & 1) * STAGE_B,
                                      Ah, Al, Bh, Bl, rowBase, colBase,
                                      (c + 1) * 32, N, K, tid);

#pragma unroll
        for (int ks = 0; ks < 2; ks++) {
            uint32_t ah[2][4], al[2][4];
#pragma unroll
            for (int mt = 0; mt < 2; mt++) {
                uint32_t off = (uint32_t)(wm * 32 + mt * 16 + (lane & 15)) * A_STRIDE_B
                             + (uint32_t)(ks * 16 + (lane >> 4) * 8) * 2;
                ldsm_x4(ah[mt], aH + off);
                if (SPLIT == 3) ldsm_x4(al[mt], aL + off);
            }
#pragma unroll
            for (int p = 0; p < 4; p++) {
                uint32_t off;
                if (TRANSB) {
                    off = (uint32_t)(wn * 64 + p * 16 + (lane & 7) + ((lane >> 4) & 1) * 8) * A_STRIDE_B
                        + (uint32_t)(ks * 16 + ((lane >> 3) & 1) * 8) * 2;
                } else {
                    off = (uint32_t)(ks * 16 + (lane & 7) + ((lane >> 3) & 1) * 8) * BNN_STRIDE_B
                        + (uint32_t)(wn * 64 + p * 16 + (lane >> 4) * 8) * 2;
                }
                uint32_t bh[4];
                if (TRANSB) ldsm_x4(bh, bH + off); else ldsm_x4_t(bh, bH + off);
                if (SPLIT == 1) {
#pragma unroll
                    for (int mt = 0; mt < 2; mt++)
#pragma unroll
                        for (int g = 0; g < 2; g++)
                            mma_f16(acc[mt][p * 2 + g], ah[mt], bh + 2 * g);
                } else {
                    uint32_t bl[4];
                    // HH
#pragma unroll
                    for (int mt = 0; mt < 2; mt++)
#pragma unroll
                        for (int g = 0; g < 2; g++)
                            mma_bf16(acc[mt][p * 2 + g], ah[mt], bh + 2 * g);
                    if (TRANSB) ldsm_x4(bl, bL + off); else ldsm_x4_t(bl, bL + off);
                    // LH
#pragma unroll
                    for (int mt = 0; mt < 2; mt++)
#pragma unroll
                        for (int g = 0; g < 2; g++)
                            mma_bf16(acc[mt][p * 2 + g], al[mt], bh + 2 * g);
                    // HL
#pragma unroll
                    for (int mt = 0; mt < 2; mt++)
#pragma unroll
                        for (int g = 0; g < 2; g++)
                            mma_bf16(acc[mt][p * 2 + g], ah[mt], bl + 2 * g);
                }
            }
        }
        __syncthreads();
    }

    // ---- epilogue
#pragma unroll
    for (int mt = 0; mt < 2; mt++) {
        int r0 = rowBase + wm * 32 + mt * 16 + (lane >> 2);
#pragma unroll
        for (int ng = 0; ng < 8; ng++) {
            int col = colBase + wn * 64 + ng * 8 + (lane & 3) * 2;
            float2 v0, v1;
            v0.x = alpha * acc[mt][ng][0];
            v0.y = alpha * acc[mt][ng][1];
            v1.x = alpha * acc[mt][ng][2];
            v1.y = alpha * acc[mt][ng][3];
            if (bias) {
                float2 bb = *(const float2*)&bias[col];
                v0.x += bb.x; v0.y += bb.y;
                v1.x += bb.x; v1.y += bb.y;
            }
            if (RELU) {
                v0.x = fmaxf(v0.x, 0.f); v0.y = fmaxf(v0.y, 0.f);
                v1.x = fmaxf(v1.x, 0.f); v1.y = fmaxf(v1.y, 0.f);
            }
            if (OMODE == 0) {
                float2 w0 = v0, w1 = v1;
                if (Rres) {
                    float2 q0 = *(const float2*)&Rres[(size_t)r0 * N + col];
                    float2 q1 = *(const float2*)&Rres[(size_t)(r0 + 8) * N + col];
                    w0.x += q0.x; w0.y += q0.y;
                    w1.x += q1.x; w1.y += q1.y;
                }
                *(float2*)&Cf[(size_t)r0 * N + col]       = w0;
                *(float2*)&Cf[(size_t)(r0 + 8) * N + col] = w1;
            } else if (OMODE == 1) {
                bf16 h0 = __float2bfloat16(v0.x);
                bf16 h1 = __float2bfloat16(v0.y);
                bf16 h2 = __float2bfloat16(v1.x);
                bf16 h3 = __float2bfloat16(v1.y);
                *(uint32_t*)&C16h[(size_t)r0 * N + col] = pack2(h0, h1);
                *(uint32_t*)&C16h[(size_t)(r0 + 8) * N + col] = pack2(h2, h3);
                *(uint32_t*)&C16l[(size_t)r0 * N + col] =
                    pack2(__float2bfloat16(v0.x - __bfloat162float(h0)),
                          __float2bfloat16(v0.y - __bfloat162float(h1)));
                *(uint32_t*)&C16l[(size_t)(r0 + 8) * N + col] =
                    pack2(__float2bfloat16(v1.x - __bfloat162float(h2)),
                          __float2bfloat16(v1.y - __bfloat162float(h3)));
            } else {
                *(uint32_t*)&C16h[(size_t)r0 * N + col]       = pack2h(v0.x, v0.y);
                *(uint32_t*)&C16h[(size_t)(r0 + 8) * N + col] = pack2h(v1.x, v1.y);
            }
        }
    }
}

// ---------------------------------------------------------------------------
// Host launcher
// ---------------------------------------------------------------------------
extern "C" void kernel_launch(void* const* d_in, const int* in_sizes, int n_in,
                              void* d_out, int out_size)
{
    const int*   tokens = (const int*)  d_in[0];
    const float* emb    = (const float*)d_in[1];
    const float* Wq     = (const float*)d_in[2];
    const float* bq     = (const float*)d_in[3];
    const float* Wk     = (const float*)d_in[4];
    const float* bk     = (const float*)d_in[5];
    const float* Wv     = (const float*)d_in[6];
    const float* bv     = (const float*)d_in[7];
    const float* g1     = (const float*)d_in[8];
    const float* beta1  = (const float*)d_in[9];
    const float* g2     = (const float*)d_in[10];
    const float* beta2  = (const float*)d_in[11];
    const float* W1     = (const float*)d_in[12];
    const float* bm1    = (const float*)d_in[13];
    const float* W2     = (const float*)d_in[14];
    const float* bm2    = (const float*)d_in[15];

    float* x = (float*)d_out;

    bf16 *lnH, *lnL, *hidH, *hidL;
    bf16 *WqkvH, *WqkvL, *W1H, *W1L, *W2H, *W2L;
    __half *qkv16, *at16;
    float *sc, *bqkv;
    cudaGetSymbolAddress((void**)&lnH,   g_lnH);
    cudaGetSymbolAddress((void**)&lnL,   g_lnL);
    cudaGetSymbolAddress((void**)&qkv16, g_qkv16);
    cudaGetSymbolAddress((void**)&sc,    g_sc);
    cudaGetSymbolAddress((void**)&at16,  g_at16);
    cudaGetSymbolAddress((void**)&hidH,  g_hidH);
    cudaGetSymbolAddress((void**)&hidL,  g_hidL);
    cudaGetSymbolAddress((void**)&WqkvH, g_WqkvH);
    cudaGetSymbolAddress((void**)&WqkvL, g_WqkvL);
    cudaGetSymbolAddress((void**)&W1H,   g_W1H);
    cudaGetSymbolAddress((void**)&W1L,   g_W1L);
    cudaGetSymbolAddress((void**)&W2H,   g_W2H);
    cudaGetSymbolAddress((void**)&W2L,   g_W2L);
    cudaGetSymbolAddress((void**)&bqkv,  g_bqkv);

    cudaFuncSetAttribute(tc_gemm<3, false, false, 2>,
                         cudaFuncAttributeMaxDynamicSharedMemorySize, TC_SMEM);
    cudaFuncSetAttribute(tc_gemm<1, true, false, 0>,
                         cudaFuncAttributeMaxDynamicSharedMemorySize, TC_SMEM);
    cudaFuncSetAttribute(tc_gemm<1, false, false, 0>,
                         cudaFuncAttributeMaxDynamicSharedMemorySize, TC_SMEM);
    cudaFuncSetAttribute(tc_gemm<3, false, true, 1>,
                         cudaFuncAttributeMaxDynamicSharedMemorySize, TC_SMEM);
    cudaFuncSetAttribute(tc_gemm<3, false, false, 0>,
                         cudaFuncAttributeMaxDynamicSharedMemorySize, TC_SMEM);

    const long long TD = (long long)SEQ * D_MODEL;
    const long long SS = (long long)SEQ * SEQ;
    const float inv_sqrt_d = 0.03125f;

    __half* q16 = qkv16;
    __half* k16 = qkv16 + (size_t)NTOK * D_MODEL;
    __half* v16 = qkv16 + 2 * (size_t)NTOK * D_MODEL;

    // ---- pre-split weights & biases
    {
        int S4 = D_MODEL * D_MODEL / 4;
        int nq = NLAYERS * S4;
        int n1 = NLAYERS * D_MODEL * DFF / 4;
        split_qkv_kernel<<<nq / 256, 256>>>(Wq, WqkvH, WqkvL, nq, S4, 0);
        split_qkv_kernel<<<nq / 256, 256>>>(Wk, WqkvH, WqkvL, nq, S4, 1);
        split_qkv_kernel<<<nq / 256, 256>>>(Wv, WqkvH, WqkvL, nq, S4, 2);
        split_kernel<<<n1 / 256, 256>>>(W1, W1H, W1L, n1);
        split_kernel<<<n1 / 256, 256>>>(W2, W2H, W2L, n1);
        concat_bias_kernel<<<NLAYERS * D_MODEL / 256, 256>>>(bq, bk, bv, bqkv);
    }

    embed_kernel<<<NTOK, 256>>>(tokens, emb, x);

    for (int l = 0; l < NLAYERS; l++) {
        size_t oQ = (size_t)l * 3 * D_MODEL * D_MODEL;
        size_t o1 = (size_t)l * D_MODEL * DFF;

        ln_kernel<<<NTOK, 256>>>(x, g1 + l * D_MODEL, beta1 + l * D_MODEL, lnH, lnL);

        // fused QKV -> fp16 q,k,v
        dim3 gQKV(D_MODEL / 128, NTOK / 128, 3);
        tc_gemm<3, false, false, 2><<<gQKV, 256, TC_SMEM>>>(
            lnH, lnL, WqkvH + oQ, WqkvL + oQ, nullptr,
            (bf16*)qkv16, nullptr,
            bqkv + (size_t)l * 3 * D_MODEL, nullptr,
            NTOK, D_MODEL, D_MODEL, 1.f,
            0, (long long)D_MODEL * D_MODEL, (long long)NTOK * D_MODEL, D_MODEL);

        // scores = q @ k^T / sqrt(D)  (fp16 single-pass)
        dim3 gSC(SEQ / 128, SEQ / 128, BATCH);
        tc_gemm<1, true, false, 0><<<gSC, 256, TC_SMEM>>>(
            (const bf16*)q16, nullptr, (const bf16*)k16, nullptr,
            sc, nullptr, nullptr, nullptr, nullptr,
            SEQ, SEQ, D_MODEL, inv_sqrt_d, TD, TD, SS, 0);

        softmax_kernel<<<BATCH * SEQ, 256>>>(sc, at16);

        // x += attn @ v  (fp16 single-pass, fused residual)
        dim3 gAV(D_MODEL / 128, SEQ / 128, BATCH);
        tc_gemm<1, false, false, 0><<<gAV, 256, TC_SMEM>>>(
            (const bf16*)at16, nullptr, (const bf16*)v16, nullptr,
            x, nullptr, nullptr, nullptr, x,
            SEQ, D_MODEL, SEQ, 1.f, SS, TD, TD, 0);

        ln_kernel<<<NTOK, 256>>>(x, g2 + l * D_MODEL, beta2 + l * D_MODEL, lnH, lnL);

        dim3 gM1(DFF / 128, NTOK / 128, 1);
        tc_gemm<3, false, true, 1><<<gM1, 256, TC_SMEM>>>(
            lnH, lnL, W1H + o1, W1L + o1, nullptr, hidH, hidL,
            bm1 + l * DFF, nullptr, NTOK, DFF, D_MODEL, 1.f, 0, 0, 0, 0);

        dim3 gM2(D_MODEL / 128, NTOK / 128, 1);
        tc_gemm<3, false, false, 0><<<gM2, 256, TC_SMEM>>>(
            hidH, hidL, W2H + o1, W2L + o1, x, nullptr, nullptr,
            bm2 + l * D_MODEL, x, NTOK, D_MODEL, DFF, 1.f, 0, 0, 0, 0);
    }
}

// round 8
// speedup vs baseline: 7.1668x; 2.0229x over previous
#include <cuda_runtime.h>
#include <cuda_fp16.h>
#include <math.h>
#include <stdint.h>

// ---------------------------------------------------------------------------
// Problem constants
// ---------------------------------------------------------------------------
#define D_MODEL 1024
#define DFF     4096
#define NLAYERS 8
#define BATCH   4
#define SEQ     2048
#define NTOK    (BATCH * SEQ)      // 8192
#define EPS     1e-5f

// ---------------------------------------------------------------------------
// Device scratch (allocation-free rule: __device__ globals)
// ---------------------------------------------------------------------------
__device__ __half g_ln16 [NTOK * D_MODEL];
__device__ __half g_qkv16[3 * NTOK * D_MODEL];
__device__ float  g_sc   [BATCH * SEQ * SEQ];
__device__ __half g_at16 [BATCH * SEQ * SEQ];
__device__ __half g_hid16[NTOK * DFF];
// fp16 weights; QKV interleaved per layer: [L][3][D*D]
__device__ __half g_Wqkv16[NLAYERS * 3 * D_MODEL * D_MODEL];
__device__ __half g_W116[NLAYERS * D_MODEL * DFF];
__device__ __half g_W216[NLAYERS * DFF * D_MODEL];
__device__ float  g_bqkv[NLAYERS * 3 * D_MODEL];

// ---------------------------------------------------------------------------
// PTX helpers
// ---------------------------------------------------------------------------
__device__ __forceinline__ uint32_t smem_u32(const void* p) {
    uint32_t a;
    asm("{ .reg .u64 t; cvta.to.shared.u64 t, %1; cvt.u32.u64 %0, t; }"
        : "=r"(a) : "l"(p));
    return a;
}

__device__ __forceinline__ void ldsm_x4(uint32_t* r, uint32_t addr) {
    asm volatile("ldmatrix.sync.aligned.m8n8.x4.shared.b16 {%0,%1,%2,%3}, [%4];"
                 : "=r"(r[0]), "=r"(r[1]), "=r"(r[2]), "=r"(r[3]) : "r"(addr));
}

__device__ __forceinline__ void ldsm_x4_t(uint32_t* r, uint32_t addr) {
    asm volatile("ldmatrix.sync.aligned.m8n8.x4.trans.shared.b16 {%0,%1,%2,%3}, [%4];"
                 : "=r"(r[0]), "=r"(r[1]), "=r"(r[2]), "=r"(r[3]) : "r"(addr));
}

__device__ __forceinline__ void mma_f16(float* c, const uint32_t* a, const uint32_t* b) {
    asm volatile(
        "mma.sync.aligned.m16n8k16.row.col.f32.f16.f16.f32 "
        "{%0,%1,%2,%3}, {%4,%5,%6,%7}, {%8,%9}, {%0,%1,%2,%3};"
        : "+f"(c[0]), "+f"(c[1]), "+f"(c[2]), "+f"(c[3])
        : "r"(a[0]), "r"(a[1]), "r"(a[2]), "r"(a[3]), "r"(b[0]), "r"(b[1]));
}

__device__ __forceinline__ void cp_async16(uint32_t saddr, const void* gptr) {
    asm volatile("cp.async.cg.shared.global [%0], [%1], 16;"
                 :: "r"(saddr), "l"(gptr) : "memory");
}
__device__ __forceinline__ void cp_commit() {
    asm volatile("cp.async.commit_group;" ::: "memory");
}
__device__ __forceinline__ void cp_wait_all() {
    asm volatile("cp.async.wait_group 0;" ::: "memory");
}

__device__ __forceinline__ uint32_t pack2h(float a, float b) {
    __half ha = __float2half_rn(a), hb = __float2half_rn(b);
    return ((uint32_t)__half_as_ushort(hb) << 16) | __half_as_ushort(ha);
}

// ---------------------------------------------------------------------------
// Weight conversion kernels (fp32 -> fp16)
// ---------------------------------------------------------------------------
__global__ __launch_bounds__(256)
void conv_kernel(const float* __restrict__ in, __half* __restrict__ out, int n4)
{
    int i = blockIdx.x * 256 + threadIdx.x;
    if (i >= n4) return;
    float4 v = ((const float4*)in)[i];
    ((uint2*)out)[i] = make_uint2(pack2h(v.x, v.y), pack2h(v.z, v.w));
}

// interleave per-layer: src [L][S], dst [L][3][S] slot j
__global__ __launch_bounds__(256)
void conv_qkv_kernel(const float* __restrict__ in, __half* __restrict__ out,
                     int n4, int S4, int j)
{
    int i = blockIdx.x * 256 + threadIdx.x;
    if (i >= n4) return;
    int l = i / S4;
    int rem = i - l * S4;
    int d = (l * 3 + j) * S4 + rem;
    float4 v = ((const float4*)in)[i];
    ((uint2*)out)[d] = make_uint2(pack2h(v.x, v.y), pack2h(v.z, v.w));
}

__global__ __launch_bounds__(256)
void concat_bias_kernel(const float* __restrict__ bq,
                        const float* __restrict__ bk,
                        const float* __restrict__ bv,
                        float* __restrict__ out)
{
    int i = blockIdx.x * 256 + threadIdx.x;
    int l = i / D_MODEL;
    int d = i - l * D_MODEL;
    out[(l * 3 + 0) * D_MODEL + d] = bq[i];
    out[(l * 3 + 1) * D_MODEL + d] = bk[i];
    out[(l * 3 + 2) * D_MODEL + d] = bv[i];
}

// ---------------------------------------------------------------------------
// Embedding + sinusoidal PE
// ---------------------------------------------------------------------------
__global__ __launch_bounds__(256)
void embed_kernel(const int* __restrict__ tokens,
                  const float* __restrict__ emb,
                  float* __restrict__ out)
{
    int row = blockIdx.x;
    int s   = row & (SEQ - 1);
    int tok = tokens[row];
    int d   = threadIdx.x * 4;

    float4 e = *(const float4*)&emb[(size_t)tok * D_MODEL + d];
    float o[4] = { e.x, e.y, e.z, e.w };
#pragma unroll
    for (int i = 0; i < 4; i++) {
        int dd = d + i;
        float freq = expf((float)(dd & ~1) * (-9.210340371976184f / (float)D_MODEL));
        float a = (float)s * freq;
        o[i] += (dd & 1) ? cosf(a) : sinf(a);
    }
    *(float4*)&out[(size_t)row * D_MODEL + d] = make_float4(o[0], o[1], o[2], o[3]);
}

// ---------------------------------------------------------------------------
// LayerNorm: fp32 in -> fp16 out
// ---------------------------------------------------------------------------
__global__ __launch_bounds__(256)
void ln_kernel(const float* __restrict__ x,
               const float* __restrict__ g,
               const float* __restrict__ b,
               __half* __restrict__ out)
{
    __shared__ float red[8];
    __shared__ float s_stat;

    int row = blockIdx.x;
    int tid = threadIdx.x;
    const float4* xr = (const float4*)(x + (size_t)row * D_MODEL);
    float4 v = xr[tid];

    float s = v.x + v.y + v.z + v.w;
#pragma unroll
    for (int o = 16; o > 0; o >>= 1) s += __shfl_xor_sync(0xffffffffu, s, o);
    if ((tid & 31) == 0) red[tid >> 5] = s;
    __syncthreads();
    if (tid == 0) {
        float t = 0.f;
#pragma unroll
        for (int i = 0; i < 8; i++) t += red[i];
        s_stat = t * (1.0f / D_MODEL);
    }
    __syncthreads();
    float mean = s_stat;

    float4 d;
    d.x = v.x - mean; d.y = v.y - mean; d.z = v.z - mean; d.w = v.w - mean;

    float s2 = d.x * d.x + d.y * d.y + d.z * d.z + d.w * d.w;
#pragma unroll
    for (int o = 16; o > 0; o >>= 1) s2 += __shfl_xor_sync(0xffffffffu, s2, o);
    if ((tid & 31) == 0) red[tid >> 5] = s2;
    __syncthreads();
    if (tid == 0) {
        float t = 0.f;
#pragma unroll
        for (int i = 0; i < 8; i++) t += red[i];
        s_stat = rsqrtf(t * (1.0f / D_MODEL) + EPS);
    }
    __syncthreads();
    float rstd = s_stat;

    float4 gg = *(const float4*)&g[tid * 4];
    float4 bb = *(const float4*)&b[tid * 4];
    float4 o4;
    o4.x = d.x * rstd * gg.x + bb.x;
    o4.y = d.y * rstd * gg.y + bb.y;
    o4.z = d.z * rstd * gg.z + bb.z;
    o4.w = d.w * rstd * gg.w + bb.w;

    ((uint2*)(out + (size_t)row * D_MODEL))[tid] =
        make_uint2(pack2h(o4.x, o4.y), pack2h(o4.z, o4.w));
}

// ---------------------------------------------------------------------------
// Softmax: fp32 in -> fp16 out
// ---------------------------------------------------------------------------
__global__ __launch_bounds__(256)
void softmax_kernel(const float* __restrict__ sc, __half* __restrict__ oh)
{
    __shared__ float red[8];
    __shared__ float s_val;

    size_t row = blockIdx.x;
    const float4* p = (const float4*)(sc + row * SEQ);
    int tid = threadIdx.x;

    float4 v0 = p[tid];
    float4 v1 = p[tid + 256];

    float m = fmaxf(fmaxf(fmaxf(v0.x, v0.y), fmaxf(v0.z, v0.w)),
                    fmaxf(fmaxf(v1.x, v1.y), fmaxf(v1.z, v1.w)));
#pragma unroll
    for (int o = 16; o > 0; o >>= 1) m = fmaxf(m, __shfl_xor_sync(0xffffffffu, m, o));
    if ((tid & 31) == 0) red[tid >> 5] = m;
    __syncthreads();
    if (tid == 0) {
        float t = red[0];
#pragma unroll
        for (int i = 1; i < 8; i++) t = fmaxf(t, red[i]);
        s_val = t;
    }
    __syncthreads();
    m = s_val;

    v0.x = expf(v0.x - m); v0.y = expf(v0.y - m);
    v0.z = expf(v0.z - m); v0.w = expf(v0.w - m);
    v1.x = expf(v1.x - m); v1.y = expf(v1.y - m);
    v1.z = expf(v1.z - m); v1.w = expf(v1.w - m);

    float s = v0.x + v0.y + v0.z + v0.w + v1.x + v1.y + v1.z + v1.w;
#pragma unroll
    for (int o = 16; o > 0; o >>= 1) s += __shfl_xor_sync(0xffffffffu, s, o);
    if ((tid & 31) == 0) red[tid >> 5] = s;
    __syncthreads();
    if (tid == 0) {
        float t = 0.f;
#pragma unroll
        for (int i = 0; i < 8; i++) t += red[i];
        s_val = t;
    }
    __syncthreads();
    float inv = 1.0f / s_val;

    ((uint2*)(oh + row * SEQ))[tid] =
        make_uint2(pack2h(v0.x * inv, v0.y * inv), pack2h(v0.z * inv, v0.w * inv));
    ((uint2*)(oh + row * SEQ))[tid + 256] =
        make_uint2(pack2h(v1.x * inv, v1.y * inv), pack2h(v1.z * inv, v1.w * inv));
}

// ---------------------------------------------------------------------------
// fp16 single-pass warp-MMA GEMM, 2 CTAs/SM.
// C = alpha * A @ op(B) (+bias) (relu); OMODE 0 = fp32 out (+residual),
// OMODE 2 = fp16 out. 128x128 tile, BK=32, 8 warps (4M x 2N), cp.async
// double-buffered.
// ---------------------------------------------------------------------------
#define A_STRIDE_B   80          // bytes per K-major fp16 row (32 data + 8 pad)
#define A_TILE_B     10240       // 128 * 80
#define BNN_STRIDE_B 272         // bytes per NN fp16 row (128 data + 8 pad)
#define BNN_TILE_B   8704        // 32 * 272
#define STAGE_B      20480
#define TC_SMEM      (2 * STAGE_B)   // 40960

template<bool TRANSB>
__device__ __forceinline__ void load_chunk(
    uint32_t stg, const __half* A, const __half* B,
    int rowBase, int colBase, int kb, int N, int K, int tid)
{
    const uint32_t aS = stg;
    const uint32_t bS = stg + A_TILE_B;

#pragma unroll
    for (int i = 0; i < 2; i++) {
        int id = tid + (i << 8);
        int r = id >> 2;
        int c8 = (id & 3) << 3;
        cp_async16(aS + (uint32_t)r * A_STRIDE_B + (uint32_t)(c8 << 1),
                   A + (size_t)(rowBase + r) * K + kb + c8);
    }
    if (TRANSB) {
#pragma unroll
        for (int i = 0; i < 2; i++) {
            int id = tid + (i << 8);
            int r = id >> 2;
            int c8 = (id & 3) << 3;
            cp_async16(bS + (uint32_t)r * A_STRIDE_B + (uint32_t)(c8 << 1),
                       B + (size_t)(colBase + r) * K + kb + c8);
        }
    } else {
#pragma unroll
        for (int i = 0; i < 2; i++) {
            int id = tid + (i << 8);
            int r = id >> 4;
            int c8 = (id & 15) << 3;
            cp_async16(bS + (uint32_t)r * BNN_STRIDE_B + (uint32_t)(c8 << 1),
                       B + (size_t)(kb + r) * N + colBase + c8);
        }
    }
    cp_commit();
}

template<bool TRANSB, bool RELU, int OMODE>
__global__ __launch_bounds__(256, 2)
void tc_gemm(const __half* __restrict__ A, const __half* __restrict__ B,
             float* __restrict__ Cf, __half* __restrict__ C16,
             const float* __restrict__ bias,
             const float* __restrict__ residual,
             int M, int N, int K, float alpha,
             long long strA, long long strB, long long strC, long long strBias)
{
    extern __shared__ char smem[];
    const uint32_t sb = smem_u32(smem);
    const int tid  = threadIdx.x;
    const int wid  = tid >> 5;
    const int lane = tid & 31;
    const int wm   = wid >> 1;
    const int wn   = wid & 1;

    long long bz = blockIdx.z;
    A += bz * strA;
    B += bz * strB;
    if (OMODE == 0) Cf += bz * strC; else C16 += bz * strC;
    if (bias) bias += bz * strBias;
    const float* Rres = (OMODE == 0 && residual) ? residual + bz * strC : nullptr;

    const int rowBase = blockIdx.y * 128;
    const int colBase = blockIdx.x * 128;

    float acc[2][8][4];
#pragma unroll
    for (int i = 0; i < 2; i++)
#pragma unroll
        for (int j = 0; j < 8; j++)
#pragma unroll
            for (int t = 0; t < 4; t++) acc[i][j][t] = 0.f;

    const int nch = K >> 5;

    load_chunk<TRANSB>(sb, A, B, rowBase, colBase, 0, N, K, tid);

    for (int c = 0; c < nch; c++) {
        const uint32_t stg = sb + (uint32_t)(c & 1) * STAGE_B;
        const uint32_t aS = stg;
        const uint32_t bS = stg + A_TILE_B;

        cp_wait_all();
        __syncthreads();

        if (c + 1 < nch)
            load_chunk<TRANSB>(sb + (uint32_t)((c + 1) & 1) * STAGE_B,
                               A, B, rowBase, colBase, (c + 1) * 32, N, K, tid);

#pragma unroll
        for (int ks = 0; ks < 2; ks++) {
            uint32_t af[2][4];
#pragma unroll
            for (int mt = 0; mt < 2; mt++) {
                uint32_t off = (uint32_t)(wm * 32 + mt * 16 + (lane & 15)) * A_STRIDE_B
                             + (uint32_t)(ks * 16 + (lane >> 4) * 8) * 2;
                ldsm_x4(af[mt], aS + off);
            }
#pragma unroll
            for (int p = 0; p < 4; p++) {
                uint32_t bf[4];
                if (TRANSB) {
                    uint32_t off = (uint32_t)(wn * 64 + p * 16 + (lane & 7) + ((lane >> 4) & 1) * 8) * A_STRIDE_B
                                 + (uint32_t)(ks * 16 + ((lane >> 3) & 1) * 8) * 2;
                    ldsm_x4(bf, bS + off);
                } else {
                    uint32_t off = (uint32_t)(ks * 16 + (lane & 7) + ((lane >> 3) & 1) * 8) * BNN_STRIDE_B
                                 + (uint32_t)(wn * 64 + p * 16 + (lane >> 4) * 8) * 2;
                    ldsm_x4_t(bf, bS + off);
                }
#pragma unroll
                for (int mt = 0; mt < 2; mt++)
#pragma unroll
                    for (int g = 0; g < 2; g++)
                        mma_f16(acc[mt][p * 2 + g], af[mt], bf + 2 * g);
            }
        }
        __syncthreads();
    }

    // ---- epilogue
#pragma unroll
    for (int mt = 0; mt < 2; mt++) {
        int r0 = rowBase + wm * 32 + mt * 16 + (lane >> 2);
#pragma unroll
        for (int ng = 0; ng < 8; ng++) {
            int col = colBase + wn * 64 + ng * 8 + (lane & 3) * 2;
            float2 v0, v1;
            v0.x = alpha * acc[mt][ng][0];
            v0.y = alpha * acc[mt][ng][1];
            v1.x = alpha * acc[mt][ng][2];
            v1.y = alpha * acc[mt][ng][3];
            if (bias) {
                float2 bb = *(const float2*)&bias[col];
                v0.x += bb.x; v0.y += bb.y;
                v1.x += bb.x; v1.y += bb.y;
            }
            if (RELU) {
                v0.x = fmaxf(v0.x, 0.f); v0.y = fmaxf(v0.y, 0.f);
                v1.x = fmaxf(v1.x, 0.f); v1.y = fmaxf(v1.y, 0.f);
            }
            if (OMODE == 0) {
                if (Rres) {
                    float2 q0 = *(const float2*)&Rres[(size_t)r0 * N + col];
                    float2 q1 = *(const float2*)&Rres[(size_t)(r0 + 8) * N + col];
                    v0.x += q0.x; v0.y += q0.y;
                    v1.x += q1.x; v1.y += q1.y;
                }
                *(float2*)&Cf[(size_t)r0 * N + col]       = v0;
                *(float2*)&Cf[(size_t)(r0 + 8) * N + col] = v1;
            } else {
                *(uint32_t*)&C16[(size_t)r0 * N + col]       = pack2h(v0.x, v0.y);
                *(uint32_t*)&C16[(size_t)(r0 + 8) * N + col] = pack2h(v1.x, v1.y);
            }
        }
    }
}

// ---------------------------------------------------------------------------
// Host launcher
// ---------------------------------------------------------------------------
extern "C" void kernel_launch(void* const* d_in, const int* in_sizes, int n_in,
                              void* d_out, int out_size)
{
    const int*   tokens = (const int*)  d_in[0];
    const float* emb    = (const float*)d_in[1];
    const float* Wq     = (const float*)d_in[2];
    const float* bq     = (const float*)d_in[3];
    const float* Wk     = (const float*)d_in[4];
    const float* bk     = (const float*)d_in[5];
    const float* Wv     = (const float*)d_in[6];
    const float* bv     = (const float*)d_in[7];
    const float* g1     = (const float*)d_in[8];
    const float* beta1  = (const float*)d_in[9];
    const float* g2     = (const float*)d_in[10];
    const float* beta2  = (const float*)d_in[11];
    const float* W1     = (const float*)d_in[12];
    const float* bm1    = (const float*)d_in[13];
    const float* W2     = (const float*)d_in[14];
    const float* bm2    = (const float*)d_in[15];

    float* x = (float*)d_out;

    __half *ln16, *qkv16, *at16, *hid16, *Wqkv16, *W116, *W216;
    float *sc, *bqkv;
    cudaGetSymbolAddress((void**)&ln16,   g_ln16);
    cudaGetSymbolAddress((void**)&qkv16,  g_qkv16);
    cudaGetSymbolAddress((void**)&sc,     g_sc);
    cudaGetSymbolAddress((void**)&at16,   g_at16);
    cudaGetSymbolAddress((void**)&hid16,  g_hid16);
    cudaGetSymbolAddress((void**)&Wqkv16, g_Wqkv16);
    cudaGetSymbolAddress((void**)&W116,   g_W116);
    cudaGetSymbolAddress((void**)&W216,   g_W216);
    cudaGetSymbolAddress((void**)&bqkv,   g_bqkv);

    cudaFuncSetAttribute(tc_gemm<false, false, 2>,
                         cudaFuncAttributeMaxDynamicSharedMemorySize, TC_SMEM);
    cudaFuncSetAttribute(tc_gemm<true, false, 0>,
                         cudaFuncAttributeMaxDynamicSharedMemorySize, TC_SMEM);
    cudaFuncSetAttribute(tc_gemm<false, false, 0>,
                         cudaFuncAttributeMaxDynamicSharedMemorySize, TC_SMEM);
    cudaFuncSetAttribute(tc_gemm<false, true, 2>,
                         cudaFuncAttributeMaxDynamicSharedMemorySize, TC_SMEM);

    const long long TD = (long long)SEQ * D_MODEL;
    const long long SS = (long long)SEQ * SEQ;
    const float inv_sqrt_d = 0.03125f;

    __half* q16 = qkv16;
    __half* k16 = qkv16 + (size_t)NTOK * D_MODEL;
    __half* v16 = qkv16 + 2 * (size_t)NTOK * D_MODEL;

    // ---- convert weights & biases to fp16
    {
        int S4 = D_MODEL * D_MODEL / 4;
        int nq = NLAYERS * S4;
        int n1 = NLAYERS * D_MODEL * DFF / 4;
        conv_qkv_kernel<<<nq / 256, 256>>>(Wq, Wqkv16, nq, S4, 0);
        conv_qkv_kernel<<<nq / 256, 256>>>(Wk, Wqkv16, nq, S4, 1);
        conv_qkv_kernel<<<nq / 256, 256>>>(Wv, Wqkv16, nq, S4, 2);
        conv_kernel<<<n1 / 256, 256>>>(W1, W116, n1);
        conv_kernel<<<n1 / 256, 256>>>(W2, W216, n1);
        concat_bias_kernel<<<NLAYERS * D_MODEL / 256, 256>>>(bq, bk, bv, bqkv);
    }

    embed_kernel<<<NTOK, 256>>>(tokens, emb, x);

    for (int l = 0; l < NLAYERS; l++) {
        size_t oQ = (size_t)l * 3 * D_MODEL * D_MODEL;
        size_t o1 = (size_t)l * D_MODEL * DFF;

        ln_kernel<<<NTOK, 256>>>(x, g1 + l * D_MODEL, beta1 + l * D_MODEL, ln16);

        // fused QKV -> fp16 q,k,v
        dim3 gQKV(D_MODEL / 128, NTOK / 128, 3);
        tc_gemm<false, false, 2><<<gQKV, 256, TC_SMEM>>>(
            ln16, Wqkv16 + oQ, nullptr, qkv16,
            bqkv + (size_t)l * 3 * D_MODEL, nullptr,
            NTOK, D_MODEL, D_MODEL, 1.f,
            0, (long long)D_MODEL * D_MODEL, (long long)NTOK * D_MODEL, D_MODEL);

        // scores = q @ k^T / sqrt(D)
        dim3 gSC(SEQ / 128, SEQ / 128, BATCH);
        tc_gemm<true, false, 0><<<gSC, 256, TC_SMEM>>>(
            q16, k16, sc, nullptr, nullptr, nullptr,
            SEQ, SEQ, D_MODEL, inv_sqrt_d, TD, TD, SS, 0);

        softmax_kernel<<<BATCH * SEQ, 256>>>(sc, at16);

        // x += attn @ v
        dim3 gAV(D_MODEL / 128, SEQ / 128, BATCH);
        tc_gemm<false, false, 0><<<gAV, 256, TC_SMEM>>>(
            at16, v16, x, nullptr, nullptr, x,
            SEQ, D_MODEL, SEQ, 1.f, SS, TD, TD, 0);

        ln_kernel<<<NTOK, 256>>>(x, g2 + l * D_MODEL, beta2 + l * D_MODEL, ln16);

        // hid = relu(h2 @ W1 + bm1) -> fp16
        dim3 gM1(DFF / 128, NTOK / 128, 1);
        tc_gemm<false, true, 2><<<gM1, 256, TC_SMEM>>>(
            ln16, W116 + o1, nullptr, hid16,
            bm1 + l * DFF, nullptr, NTOK, DFF, D_MODEL, 1.f, 0, 0, 0, 0);

        // x += hid @ W2 + bm2
        dim3 gM2(D_MODEL / 128, NTOK / 128, 1);
        tc_gemm<false, false, 0><<<gM2, 256, TC_SMEM>>>(
            hid16, W216 + o1, x, nullptr,
            bm2 + l * D_MODEL, x, NTOK, D_MODEL, DFF, 1.f, 0, 0, 0, 0);
    }
}